// round 1
// baseline (speedup 1.0000x reference)
#include <cuda_runtime.h>
#include <math.h>

#define TT 65536
#define DD 256
#define RR 32
#define MM 52
#define CC 64
#define NCK (TT/CC)   // 1024 chunks

// Scratch (device globals; no allocation allowed)
__device__ float g_Qt[TT*RR];   // Lambda_u * q_u
__device__ float g_Kt[TT*RR];   // (l_u/Lambda_u) * k_u
__device__ float g_Vv[TT*RR];   // v_u
__device__ float g_B [NCK*RR*RR]; // per-chunk K~^T V
__device__ float g_gm[NCK];       // per-chunk Lambda_C
__device__ float g_Sp[NCK*RR*RR]; // state BEFORE each chunk

// ---------------------------------------------------------------------------
// Kernel 1: per-chunk fused projections (K~, V, Q~) + B = K~^T V + gamma
// ---------------------------------------------------------------------------
__global__ __launch_bounds__(256, 1) void k_proj(
    const float* __restrict__ X,  const float* __restrict__ lr,
    const float* __restrict__ dec,
    const float* __restrict__ Wk, const float* __restrict__ bk,
    const float* __restrict__ Wv, const float* __restrict__ bv,
    const float* __restrict__ Wq, const float* __restrict__ bq)
{
    __shared__ float Xs[CC][33];
    __shared__ float Ws[96][33];
    __shared__ float Ks[CC][32];
    __shared__ float Vs[CC][32];
    __shared__ float Lam[CC], Lrs[CC], Dcs[CC], bcat[96];

    const int tid   = threadIdx.x;
    const int chunk = blockIdx.x;
    const int t0    = chunk * CC;

    if (tid < 96) {
        bcat[tid] = (tid < 32) ? bk[tid] : (tid < 64 ? bv[tid-32] : bq[tid-64]);
    } else if (tid < 160) {
        Lrs[tid-96] = lr[t0 + tid-96];
    } else if (tid < 224) {
        Dcs[tid-160] = dec[t0 + tid-160];
    }
    __syncthreads();
    if (tid == 0) {
        float p = 1.f;
        #pragma unroll
        for (int u = 0; u < CC; u++) { p *= (1.f - Dcs[u]); Lam[u] = p; }
    }

    const int ty = tid >> 4, tx = tid & 15;   // 16x16 thread grid
    float acc[4][6];
    #pragma unroll
    for (int a = 0; a < 4; a++)
        #pragma unroll
        for (int b = 0; b < 6; b++) acc[a][b] = 0.f;

    for (int kk0 = 0; kk0 < DD; kk0 += 32) {
        #pragma unroll
        for (int r = 0; r < 8; r++) {            // Xs: 64x32
            int idx = tid + 256*r;
            int row = idx >> 5, k = idx & 31;
            Xs[row][k] = X[(size_t)(t0+row)*DD + kk0 + k];
        }
        #pragma unroll
        for (int r = 0; r < 12; r++) {           // Ws: 96x32 (Wk|Wv|Wq stacked)
            int idx = tid + 256*r;
            int row = idx >> 5, k = idx & 31;
            const float* Wsrc = (row < 32) ? Wk : (row < 64 ? Wv : Wq);
            int rr = (row < 32) ? row : (row < 64 ? row-32 : row-64);
            Ws[row][k] = Wsrc[rr*DD + kk0 + k];
        }
        __syncthreads();
        #pragma unroll
        for (int k = 0; k < 32; k++) {
            float xr[4], wr[6];
            #pragma unroll
            for (int a = 0; a < 4; a++) xr[a] = Xs[4*ty+a][k];
            #pragma unroll
            for (int b = 0; b < 6; b++) wr[b] = Ws[6*tx+b][k];
            #pragma unroll
            for (int a = 0; a < 4; a++)
                #pragma unroll
                for (int b = 0; b < 6; b++) acc[a][b] += xr[a]*wr[b];
        }
        __syncthreads();
    }

    // Epilogue: scale + write out
    #pragma unroll
    for (int a = 0; a < 4; a++) {
        int u = 4*ty + a;
        float lam = Lam[u];
        float ksc = Lrs[u] / lam;
        size_t tb = (size_t)(t0+u) * RR;
        #pragma unroll
        for (int b = 0; b < 6; b++) {
            int c = 6*tx + b;
            float v = acc[a][b] + bcat[c];
            if (c < 32)       { float kv = ksc*v; g_Kt[tb + c] = kv; Ks[u][c] = kv; }
            else if (c < 64)  { int cc = c-32;    g_Vv[tb + cc] = v; Vs[u][cc] = v; }
            else              {                   g_Qt[tb + (c-64)] = lam*v; }
        }
    }
    __syncthreads();

    // B = K~^T V  (32x32), 4 elements per thread
    {
        int i  = tid >> 3;          // 0..31
        int j0 = (tid & 7) * 4;     // 0,4,...,28
        float b0=0.f, b1=0.f, b2=0.f, b3=0.f;
        #pragma unroll 8
        for (int u = 0; u < CC; u++) {
            float kk = Ks[u][i];
            b0 += kk * Vs[u][j0+0];
            b1 += kk * Vs[u][j0+1];
            b2 += kk * Vs[u][j0+2];
            b3 += kk * Vs[u][j0+3];
        }
        size_t base = (size_t)chunk*RR*RR + i*RR + j0;
        g_B[base+0]=b0; g_B[base+1]=b1; g_B[base+2]=b2; g_B[base+3]=b3;
        if (tid == 0) g_gm[chunk] = Lam[CC-1];
    }
}

// ---------------------------------------------------------------------------
// Kernel 2: sequential scan over 1024 chunks: S_c = gamma_c * (S_{c-1} + B_c)
// g_Sp[c] = state BEFORE chunk c
// ---------------------------------------------------------------------------
__global__ __launch_bounds__(1024, 1) void k_scan()
{
    __shared__ float gs[NCK];
    const int e = threadIdx.x;       // element (i,j) of the 32x32 state
    gs[e] = g_gm[e];                 // NCK == 1024 == blockDim
    __syncthreads();
    float s = 0.f;
    #pragma unroll 8
    for (int c = 0; c < NCK; c++) {
        g_Sp[(size_t)c*1024 + e] = s;
        s = gs[c] * (s + g_B[(size_t)c*1024 + e]);
    }
}

// ---------------------------------------------------------------------------
// Kernel 3: per-chunk A = tril(Q~ K~^T); out = Q~@S_prev + A@V; head + tanh
// ---------------------------------------------------------------------------
__global__ __launch_bounds__(256, 1) void k_out(
    const float* __restrict__ Wo, const float* __restrict__ bo,
    float* __restrict__ out)
{
    extern __shared__ float sm[];
    float* Qs  = sm;               // 64*33
    float* Ks  = Qs  + 64*33;      // 64*33
    float* Vs  = Ks  + 64*33;      // 64*33
    float* Ss  = Vs  + 64*33;      // 32*33
    float* As  = Ss  + 32*33;      // 64*65
    float* Os  = As  + 64*65;      // 64*33
    float* Wos = Os  + 64*33;      // 52*33
    float* bos = Wos + 52*33;      // 52

    const int tid   = threadIdx.x;
    const int chunk = blockIdx.x;
    const int t0    = chunk * CC;

    #pragma unroll
    for (int r = 0; r < 8; r++) {
        int idx = tid + 256*r; int u = idx >> 5, i = idx & 31;
        size_t g = (size_t)(t0+u)*RR + i;
        Qs[u*33+i] = g_Qt[g];
        Ks[u*33+i] = g_Kt[g];
        Vs[u*33+i] = g_Vv[g];
    }
    #pragma unroll
    for (int r = 0; r < 4; r++) {
        int idx = tid + 256*r; int i = idx >> 5, j = idx & 31;
        Ss[i*33+j] = g_Sp[(size_t)chunk*1024 + idx];
    }
    for (int idx = tid; idx < MM*RR; idx += 256)
        Wos[(idx >> 5)*33 + (idx & 31)] = Wo[idx];
    if (tid < MM) bos[tid] = bo[tid];
    __syncthreads();

    const int ty = tid >> 4, tx = tid & 15;

    // A = tril(Q~ K~^T): 4x4 tile per thread
    {
        float a4[4][4];
        #pragma unroll
        for (int a = 0; a < 4; a++)
            #pragma unroll
            for (int b = 0; b < 4; b++) a4[a][b] = 0.f;
        #pragma unroll
        for (int i = 0; i < 32; i++) {
            float qr[4], kr[4];
            #pragma unroll
            for (int a = 0; a < 4; a++) qr[a] = Qs[(4*ty+a)*33 + i];
            #pragma unroll
            for (int b = 0; b < 4; b++) kr[b] = Ks[(4*tx+b)*33 + i];
            #pragma unroll
            for (int a = 0; a < 4; a++)
                #pragma unroll
                for (int b = 0; b < 4; b++) a4[a][b] += qr[a]*kr[b];
        }
        #pragma unroll
        for (int a = 0; a < 4; a++)
            #pragma unroll
            for (int b = 0; b < 4; b++) {
                int u = 4*ty+a, s = 4*tx+b;
                As[u*65 + s] = (s <= u) ? a4[a][b] : 0.f;
            }
    }
    __syncthreads();

    // out = Q~@S + A@V : 4 rows x 2 cols per thread
    {
        float o[4][2];
        #pragma unroll
        for (int a = 0; a < 4; a++) { o[a][0]=0.f; o[a][1]=0.f; }
        #pragma unroll
        for (int k = 0; k < 32; k++) {
            float qr[4], sr[2];
            #pragma unroll
            for (int a = 0; a < 4; a++) qr[a] = Qs[(4*ty+a)*33 + k];
            sr[0] = Ss[k*33 + 2*tx+0];
            sr[1] = Ss[k*33 + 2*tx+1];
            #pragma unroll
            for (int a = 0; a < 4; a++) { o[a][0] += qr[a]*sr[0]; o[a][1] += qr[a]*sr[1]; }
        }
        #pragma unroll
        for (int k = 0; k < 64; k++) {
            float ar[4], vr[2];
            #pragma unroll
            for (int a = 0; a < 4; a++) ar[a] = As[(4*ty+a)*65 + k];
            vr[0] = Vs[k*33 + 2*tx+0];
            vr[1] = Vs[k*33 + 2*tx+1];
            #pragma unroll
            for (int a = 0; a < 4; a++) { o[a][0] += ar[a]*vr[0]; o[a][1] += ar[a]*vr[1]; }
        }
        #pragma unroll
        for (int a = 0; a < 4; a++) {
            Os[(4*ty+a)*33 + 2*tx+0] = o[a][0];
            Os[(4*ty+a)*33 + 2*tx+1] = o[a][1];
        }
    }
    __syncthreads();

    // head: raw = Os @ Wo^T + bo; out = 1 + tanh(raw)
    #pragma unroll
    for (int r = 0; r < 13; r++) {              // 64*52 = 3328 = 256*13
        int idx = tid + 256*r;
        int u = idx / 52, m = idx % 52;
        float accv = bos[m];
        #pragma unroll 8
        for (int j = 0; j < 32; j++) accv += Os[u*33+j] * Wos[m*33+j];
        out[(size_t)(t0+u)*MM + m] = 1.f + tanhf(accv);
    }
}

// ---------------------------------------------------------------------------
extern "C" void kernel_launch(void* const* d_in, const int* in_sizes, int n_in,
                              void* d_out, int out_size)
{
    const float* X  = (const float*)d_in[0];
    const float* lr = (const float*)d_in[1];
    const float* dc = (const float*)d_in[2];
    const float* Wk = (const float*)d_in[3];
    const float* bk = (const float*)d_in[4];
    const float* Wv = (const float*)d_in[5];
    const float* bv = (const float*)d_in[6];
    const float* Wq = (const float*)d_in[7];
    const float* bq = (const float*)d_in[8];
    const float* Wo = (const float*)d_in[9];
    const float* bo = (const float*)d_in[10];
    float* out = (float*)d_out;

    const int smem3 = (64*33*3 + 32*33 + 64*65 + 64*33 + 52*33 + 52) * (int)sizeof(float);
    cudaFuncSetAttribute(k_out, cudaFuncAttributeMaxDynamicSharedMemorySize, smem3);

    k_proj<<<NCK, 256>>>(X, lr, dc, Wk, bk, Wv, bv, Wq, bq);
    k_scan<<<1, 1024>>>();
    k_out<<<NCK, 256, smem3>>>(Wo, bo, out);
    (void)in_sizes; (void)n_in; (void)out_size;
}

// round 2
// speedup vs baseline: 1.1717x; 1.1717x over previous
#include <cuda_runtime.h>
#include <math.h>

#define TT 65536
#define DD 256
#define RR 32
#define MM 52
#define CC 64
#define NCK (TT/CC)   // 1024 chunks

// Scratch (device globals; no allocation allowed)
__device__ float g_Qt[TT*RR];     // Lambda_u * q_u
__device__ float g_Kt[TT*RR];     // (l_u/Lambda_u) * k_u
__device__ float g_Vv[TT*RR];     // v_u
__device__ float g_B [NCK*RR*RR]; // per-chunk K~^T V
__device__ float g_gm[NCK];       // per-chunk Lambda_C
__device__ float g_Sp[NCK*RR*RR]; // state BEFORE each chunk

__device__ __forceinline__ float tanh_fast(float x) {
    float y;
    asm("tanh.approx.f32 %0, %1;" : "=f"(y) : "f"(x));
    return y;
}

// ---------------------------------------------------------------------------
// Kernel 1: 2 chunks (128 rows) per block. Fused projections K~,V,Q~ + B + gamma
// 128x96 tile, 16x16 threads, 8x6 per-thread register tile.
// ---------------------------------------------------------------------------
__global__ __launch_bounds__(256, 2) void k_proj(
    const float* __restrict__ X,  const float* __restrict__ lr,
    const float* __restrict__ dec,
    const float* __restrict__ Wk, const float* __restrict__ bk,
    const float* __restrict__ Wv, const float* __restrict__ bv,
    const float* __restrict__ Wq, const float* __restrict__ bq)
{
    // Union region: (Xs 128x33 | Ws 96x33) during GEMM, (Ks 128x32 | Vs 128x32) after
    __shared__ __align__(16) float smU[8192];   // 32KB
    float (*Xs)[33] = (float(*)[33])smU;            // 4224 floats
    float (*Ws)[33] = (float(*)[33])(smU + 4224);   // 3168 floats
    __shared__ float Lam[128], Lrs[128], Dcs[128], bcat[96];

    const int tid = threadIdx.x;
    const int t0  = blockIdx.x * 128;

    if (tid < 96)
        bcat[tid] = (tid < 32) ? bk[tid] : (tid < 64 ? bv[tid-32] : bq[tid-64]);
    if (tid < 128) Lrs[tid] = lr[t0 + tid];
    else           Dcs[tid-128] = dec[t0 + tid - 128];
    __syncthreads();
    if (tid < 2) {
        float p = 1.f;
        #pragma unroll
        for (int u = 0; u < 64; u++) { p *= (1.f - Dcs[64*tid + u]); Lam[64*tid + u] = p; }
    }

    const int ty = tid >> 4, tx = tid & 15;
    float acc[8][6];
    #pragma unroll
    for (int a = 0; a < 8; a++)
        #pragma unroll
        for (int b = 0; b < 6; b++) acc[a][b] = 0.f;

    for (int kk0 = 0; kk0 < DD; kk0 += 32) {
        // Xs: 128x32 = 1024 float4 slots
        #pragma unroll
        for (int r = 0; r < 4; r++) {
            int slot = tid + 256*r;
            int row = slot >> 3, k4 = (slot & 7) * 4;
            float4 x4 = *(const float4*)&X[(size_t)(t0+row)*DD + kk0 + k4];
            Xs[row][k4+0] = x4.x; Xs[row][k4+1] = x4.y;
            Xs[row][k4+2] = x4.z; Xs[row][k4+3] = x4.w;
        }
        // Ws: 96x32 = 768 float4 slots (Wk|Wv|Wq stacked)
        #pragma unroll
        for (int r = 0; r < 3; r++) {
            int slot = tid + 256*r;
            int row = slot >> 3, k4 = (slot & 7) * 4;
            const float* Wsrc = (row < 32) ? Wk : (row < 64 ? Wv : Wq);
            float4 w4 = *(const float4*)&Wsrc[(row & 31)*DD + kk0 + k4];
            Ws[row][k4+0] = w4.x; Ws[row][k4+1] = w4.y;
            Ws[row][k4+2] = w4.z; Ws[row][k4+3] = w4.w;
        }
        __syncthreads();
        #pragma unroll
        for (int k = 0; k < 32; k++) {
            float xr[8], wr[6];
            #pragma unroll
            for (int a = 0; a < 8; a++) xr[a] = Xs[8*ty + a][k];
            #pragma unroll
            for (int b = 0; b < 6; b++) wr[b] = Ws[6*tx + b][k];
            #pragma unroll
            for (int a = 0; a < 8; a++)
                #pragma unroll
                for (int b = 0; b < 6; b++) acc[a][b] += xr[a]*wr[b];
        }
        __syncthreads();
    }

    // Epilogue: scale + write out (union region now Ks/Vs)
    float (*Ks)[32] = (float(*)[32])smU;           // 4096 floats
    float (*Vs)[32] = (float(*)[32])(smU + 4096);  // 4096 floats
    #pragma unroll
    for (int a = 0; a < 8; a++) {
        int u = 8*ty + a;
        float lam = Lam[u];
        float ksc = Lrs[u] / lam;
        size_t tb = (size_t)(t0+u) * RR;
        #pragma unroll
        for (int b = 0; b < 6; b++) {
            int c = 6*tx + b;
            float v = acc[a][b] + bcat[c];
            if (c < 32)       { float kv = ksc*v; g_Kt[tb + c] = kv; Ks[u][c] = kv; }
            else if (c < 64)  { int cc = c-32;    g_Vv[tb + cc] = v; Vs[u][cc] = v; }
            else              {                   g_Qt[tb + (c-64)] = lam*v; }
        }
    }
    __syncthreads();

    // B = K~^T V per chunk; 2 chunks, 128 threads each; 8 elems/thread
    {
        int ch = tid >> 7, l = tid & 127;
        int i  = l >> 2;            // 0..31
        int j0 = (l & 3) * 8;       // 0,8,16,24
        float b[8];
        #pragma unroll
        for (int j = 0; j < 8; j++) b[j] = 0.f;
        #pragma unroll 4
        for (int u = 0; u < CC; u++) {
            float kk = Ks[ch*64 + u][i];
            #pragma unroll
            for (int j = 0; j < 8; j++) b[j] += kk * Vs[ch*64 + u][j0 + j];
        }
        size_t base = (size_t)(blockIdx.x*2 + ch)*RR*RR + i*RR + j0;
        #pragma unroll
        for (int j = 0; j < 8; j++) g_B[base + j] = b[j];
        if (l == 0) g_gm[blockIdx.x*2 + ch] = Lam[ch*64 + 63];
    }
}

// ---------------------------------------------------------------------------
// Kernel 2: scan over 1024 chunks. 1024 independent element-chains spread
// across 32 blocks x 32 threads: s = g*(s + b) = fma(g, s, g*b).
// ---------------------------------------------------------------------------
__global__ __launch_bounds__(32, 1) void k_scan()
{
    __shared__ float gs[NCK];
    const int e = blockIdx.x * 32 + threadIdx.x;
    for (int i = threadIdx.x; i < NCK; i += 32) gs[i] = g_gm[i];
    __syncthreads();
    float s = 0.f;
    #pragma unroll 8
    for (int c = 0; c < NCK; c++) {
        g_Sp[(size_t)c*1024 + e] = s;
        float g = gs[c];
        float gb = g * g_B[(size_t)c*1024 + e];
        s = fmaf(g, s, gb);
    }
}

// ---------------------------------------------------------------------------
// Kernel 3: per-chunk A = tril(Q~ K~^T); O = Q~@S_prev + A@V; head + 1+tanh
// ---------------------------------------------------------------------------
__global__ __launch_bounds__(256, 3) void k_out(
    const float* __restrict__ Wo, const float* __restrict__ bo,
    float* __restrict__ out)
{
    extern __shared__ float sm[];
    float* Qs  = sm;               // 64*33 = 2112
    float* Vs  = Qs  + 2112;       // 64*33 = 2112
    float* Ss  = Vs  + 2112;       // 32*33 = 1056
    float* Wos = Ss  + 1056;       // 64*33 = 2112 (rows 52..63 zero)
    float* bos = Wos + 2112;       // 64
    float* KsOs= bos + 64;         // 64*33 = 2112 (Ks in phase A, Os after)
    float* As  = KsOs+ 2112;       // 64*65 = 4160
    // total 13728 floats = 54912 B

    const int tid   = threadIdx.x;
    const int chunk = blockIdx.x;
    const int t0    = chunk * CC;

    // Stage inputs (float4 loads from contiguous gmem)
    #pragma unroll
    for (int r = 0; r < 2; r++) {
        int slot = tid + 256*r;           // 512 slots = 64 rows x 8 float4
        int u = slot >> 3, j4 = (slot & 7) * 4;
        size_t g = (size_t)(t0+u)*RR + j4;
        float4 q4 = *(const float4*)&g_Qt[g];
        float4 k4 = *(const float4*)&g_Kt[g];
        float4 v4 = *(const float4*)&g_Vv[g];
        Qs [u*33+j4+0]=q4.x; Qs [u*33+j4+1]=q4.y; Qs [u*33+j4+2]=q4.z; Qs [u*33+j4+3]=q4.w;
        KsOs[u*33+j4+0]=k4.x; KsOs[u*33+j4+1]=k4.y; KsOs[u*33+j4+2]=k4.z; KsOs[u*33+j4+3]=k4.w;
        Vs [u*33+j4+0]=v4.x; Vs [u*33+j4+1]=v4.y; Vs [u*33+j4+2]=v4.z; Vs [u*33+j4+3]=v4.w;
    }
    {   // Ss: 1024 floats = 256 float4
        int i = tid >> 3, j4 = (tid & 7) * 4;
        float4 s4 = *(const float4*)&g_Sp[(size_t)chunk*1024 + tid*4];
        Ss[i*33+j4+0]=s4.x; Ss[i*33+j4+1]=s4.y; Ss[i*33+j4+2]=s4.z; Ss[i*33+j4+3]=s4.w;
    }
    #pragma unroll
    for (int r = 0; r < 8; r++) {         // Wos 64x32 (zero-padded)
        int idx = tid + 256*r;
        int m = idx >> 5, j = idx & 31;
        Wos[m*33 + j] = (m < MM) ? Wo[m*RR + j] : 0.f;
    }
    if (tid < 64) bos[tid] = (tid < MM) ? bo[tid] : 0.f;
    __syncthreads();

    const int ty = tid >> 4, tx = tid & 15;

    // Phase A: A = tril(Q~ K~^T), 4x4 per thread
    {
        float a4[4][4];
        #pragma unroll
        for (int a = 0; a < 4; a++)
            #pragma unroll
            for (int b = 0; b < 4; b++) a4[a][b] = 0.f;
        #pragma unroll
        for (int k = 0; k < 32; k++) {
            float qr[4], kr[4];
            #pragma unroll
            for (int a = 0; a < 4; a++) qr[a] = Qs[(4*ty+a)*33 + k];
            #pragma unroll
            for (int b = 0; b < 4; b++) kr[b] = KsOs[(4*tx+b)*33 + k];
            #pragma unroll
            for (int a = 0; a < 4; a++)
                #pragma unroll
                for (int b = 0; b < 4; b++) a4[a][b] += qr[a]*kr[b];
        }
        #pragma unroll
        for (int a = 0; a < 4; a++)
            #pragma unroll
            for (int b = 0; b < 4; b++) {
                int u = 4*ty+a, s = 4*tx+b;
                As[u*65 + s] = (s <= u) ? a4[a][b] : 0.f;
            }
    }
    __syncthreads();   // also retires all reads of Ks before Os overwrites it

    // Phase O: O = Q~@S + A@V, 4 rows x 2 cols per thread → Os (aliases Ks)
    {
        float o[4][2];
        #pragma unroll
        for (int a = 0; a < 4; a++) { o[a][0]=0.f; o[a][1]=0.f; }
        #pragma unroll
        for (int k = 0; k < 32; k++) {
            float s0 = Ss[k*33 + 2*tx+0], s1 = Ss[k*33 + 2*tx+1];
            #pragma unroll
            for (int a = 0; a < 4; a++) {
                float q = Qs[(4*ty+a)*33 + k];
                o[a][0] += q*s0; o[a][1] += q*s1;
            }
        }
        #pragma unroll
        for (int k = 0; k < 64; k++) {
            float v0 = Vs[k*33 + 2*tx+0], v1 = Vs[k*33 + 2*tx+1];
            #pragma unroll
            for (int a = 0; a < 4; a++) {
                float aa = As[(4*ty+a)*65 + k];
                o[a][0] += aa*v0; o[a][1] += aa*v1;
            }
        }
        __syncthreads();  // ensure all Phase-A readers done before Os write (alias)
        #pragma unroll
        for (int a = 0; a < 4; a++) {
            KsOs[(4*ty+a)*33 + 2*tx+0] = o[a][0];
            KsOs[(4*ty+a)*33 + 2*tx+1] = o[a][1];
        }
    }
    __syncthreads();

    // Head: raw = Os @ Wo^T + bo, 4x4 tile per thread; out = 1 + tanh(raw)
    {
        float h[4][4];
        #pragma unroll
        for (int a = 0; a < 4; a++)
            #pragma unroll
            for (int b = 0; b < 4; b++) h[a][b] = 0.f;
        #pragma unroll
        for (int k = 0; k < 32; k++) {
            float qr[4], wr[4];
            #pragma unroll
            for (int a = 0; a < 4; a++) qr[a] = KsOs[(4*ty+a)*33 + k];
            #pragma unroll
            for (int b = 0; b < 4; b++) wr[b] = Wos[(4*tx+b)*33 + k];
            #pragma unroll
            for (int a = 0; a < 4; a++)
                #pragma unroll
                for (int b = 0; b < 4; b++) h[a][b] += qr[a]*wr[b];
        }
        #pragma unroll
        for (int a = 0; a < 4; a++) {
            int u = 4*ty + a;
            #pragma unroll
            for (int b = 0; b < 4; b++) {
                int m = 4*tx + b;
                if (m < MM)
                    out[(size_t)(t0+u)*MM + m] = 1.f + tanh_fast(h[a][b] + bos[m]);
            }
        }
    }
}

// ---------------------------------------------------------------------------
extern "C" void kernel_launch(void* const* d_in, const int* in_sizes, int n_in,
                              void* d_out, int out_size)
{
    const float* X  = (const float*)d_in[0];
    const float* lr = (const float*)d_in[1];
    const float* dc = (const float*)d_in[2];
    const float* Wk = (const float*)d_in[3];
    const float* bk = (const float*)d_in[4];
    const float* Wv = (const float*)d_in[5];
    const float* bv = (const float*)d_in[6];
    const float* Wq = (const float*)d_in[7];
    const float* bq = (const float*)d_in[8];
    const float* Wo = (const float*)d_in[9];
    const float* bo = (const float*)d_in[10];
    float* out = (float*)d_out;

    const int smem3 = 13728 * (int)sizeof(float);
    static int done = 0;
    cudaFuncSetAttribute(k_out, cudaFuncAttributeMaxDynamicSharedMemorySize, smem3);
    (void)done;

    k_proj<<<NCK/2, 256>>>(X, lr, dc, Wk, bk, Wv, bv, Wq, bq);
    k_scan<<<32, 32>>>();
    k_out<<<NCK, 256, smem3>>>(Wo, bo, out);
    (void)in_sizes; (void)n_in; (void)out_size;
}

// round 3
// speedup vs baseline: 1.1994x; 1.0236x over previous
#include <cuda_runtime.h>
#include <cuda_bf16.h>
#include <math.h>
#include <stdint.h>

#define TT 65536
#define DD 256
#define RR 32
#define MM 52
#define CC 64
#define NCK 1024

// Scratch (device globals; no allocation allowed)
__device__ __align__(16) __nv_bfloat16 g_Qb [TT*RR];   // Lambda_u * q_u   [t][r]
__device__ __align__(16) __nv_bfloat16 g_Kb [TT*RR];   // (l/Lambda)*k     [t][r]
__device__ __align__(16) __nv_bfloat16 g_VTb[TT*RR];   // per-chunk V^T    [chunk][j=32][u=64]
__device__ __align__(16) float g_BT [NCK*RR*RR];       // per-chunk (K~^T V)^T  [chunk][j][i]
__device__ float g_gm[NCK];                            // per-chunk Lambda_C
__device__ __align__(16) float g_SpT[NCK*RR*RR];       // state^T BEFORE each chunk

__device__ __forceinline__ uint32_t packbf(float a, float b) {
    __nv_bfloat162 h = __floats2bfloat162_rn(a, b);
    return *reinterpret_cast<uint32_t*>(&h);
}
__device__ __forceinline__ float tanh_fast(float x) {
    float y; asm("tanh.approx.f32 %0, %1;" : "=f"(y) : "f"(x)); return y;
}
__device__ __forceinline__ void mma16816(float* c, const uint32_t* a, const uint32_t* b) {
    asm volatile("mma.sync.aligned.m16n8k16.row.col.f32.bf16.bf16.f32 "
        "{%0,%1,%2,%3}, {%4,%5,%6,%7}, {%8,%9}, {%0,%1,%2,%3};"
        : "+f"(c[0]), "+f"(c[1]), "+f"(c[2]), "+f"(c[3])
        : "r"(a[0]), "r"(a[1]), "r"(a[2]), "r"(a[3]), "r"(b[0]), "r"(b[1]));
}

// ---------------------------------------------------------------------------
// Kernel 1: 2 chunks (128 rows) per block. bf16 MMA projections + B + gamma
// ---------------------------------------------------------------------------
__global__ __launch_bounds__(256, 2) void k_proj(
    const float* __restrict__ X,  const float* __restrict__ lr,
    const float* __restrict__ dec,
    const float* __restrict__ Wk, const float* __restrict__ bk,
    const float* __restrict__ Wv, const float* __restrict__ bv,
    const float* __restrict__ Wq, const float* __restrict__ bq)
{
    __shared__ __align__(16) __nv_bfloat16 sXs[128*72];   // X tile (also KsT/VsT later)
    __shared__ __align__(16) __nv_bfloat16 sWs[96*72];    // W tile (Wk|Wv|Wq)
    __shared__ float Lam[128], Lrs[128], Dcs[128], bcat[96];

    const int tid  = threadIdx.x;
    const int lane = tid & 31, w = tid >> 5;
    const int g = lane >> 2, tig = lane & 3;
    const int t0 = blockIdx.x * 128;

    if (tid < 96)
        bcat[tid] = (tid < 32) ? bk[tid] : (tid < 64 ? bv[tid-32] : bq[tid-64]);
    if (tid < 128) Lrs[tid] = lr[t0 + tid];
    else           Dcs[tid-128] = dec[t0 + tid - 128];
    __syncthreads();
    if (tid < 2) {
        float p = 1.f;
        #pragma unroll
        for (int u = 0; u < 64; u++) { p *= (1.f - Dcs[64*tid + u]); Lam[64*tid + u] = p; }
    }

    const int wy = w >> 1, wx = w & 1;   // warp tile: 32 rows x 48 cols
    float acc[2][6][4];
    #pragma unroll
    for (int mi = 0; mi < 2; mi++)
        #pragma unroll
        for (int ni = 0; ni < 6; ni++)
            #pragma unroll
            for (int r = 0; r < 4; r++) acc[mi][ni][r] = 0.f;

    for (int kk0 = 0; kk0 < DD; kk0 += 64) {
        // Stage X tile 128x64 (f32 -> bf16), 8 float4 per thread
        #pragma unroll
        for (int r = 0; r < 8; r++) {
            int slot = tid + 256*r;
            int row = slot >> 4, k4 = (slot & 15) << 2;
            float4 x4 = *(const float4*)&X[(size_t)(t0+row)*DD + kk0 + k4];
            uint2 p; p.x = packbf(x4.x, x4.y); p.y = packbf(x4.z, x4.w);
            *(uint2*)&sXs[row*72 + k4] = p;
        }
        // Stage W tile 96x64
        #pragma unroll
        for (int r = 0; r < 6; r++) {
            int slot = tid + 256*r;
            int row = slot >> 4, k4 = (slot & 15) << 2;
            const float* Wsrc = (row < 32) ? Wk : (row < 64 ? Wv : Wq);
            float4 w4 = *(const float4*)&Wsrc[(row & 31)*DD + kk0 + k4];
            uint2 p; p.x = packbf(w4.x, w4.y); p.y = packbf(w4.z, w4.w);
            *(uint2*)&sWs[row*72 + k4] = p;
        }
        __syncthreads();
        #pragma unroll
        for (int ks = 0; ks < 4; ks++) {
            int kb = ks * 16;
            uint32_t a[2][4];
            #pragma unroll
            for (int mi = 0; mi < 2; mi++) {
                int rb = wy*32 + mi*16;
                a[mi][0] = *(const uint32_t*)&sXs[(rb+g  )*72 + kb +     2*tig];
                a[mi][1] = *(const uint32_t*)&sXs[(rb+8+g)*72 + kb +     2*tig];
                a[mi][2] = *(const uint32_t*)&sXs[(rb+g  )*72 + kb + 8 + 2*tig];
                a[mi][3] = *(const uint32_t*)&sXs[(rb+8+g)*72 + kb + 8 + 2*tig];
            }
            #pragma unroll
            for (int ni = 0; ni < 6; ni++) {
                int nb = wx*48 + ni*8;
                uint32_t b[2];
                b[0] = *(const uint32_t*)&sWs[(nb+g)*72 + kb +     2*tig];
                b[1] = *(const uint32_t*)&sWs[(nb+g)*72 + kb + 8 + 2*tig];
                mma16816(acc[0][ni], a[0], b);
                mma16816(acc[1][ni], a[1], b);
            }
        }
        __syncthreads();
    }

    // Epilogue: scale + write K~/V^T/Q~; KsT/VsT alias sXs (all reads done)
    __nv_bfloat16* KsT = sXs;              // [2][32][72]  K~^T per chunk
    __nv_bfloat16* VsT = sXs + 2*32*72;    // [2][32][72]  V^T per chunk
    #pragma unroll
    for (int mi = 0; mi < 2; mi++) {
        int rlo = wy*32 + mi*16 + g, rhi = rlo + 8;
        float lamL = Lam[rlo], lamH = Lam[rhi];
        float ksL = Lrs[rlo]/lamL, ksH = Lrs[rhi]/lamH;
        int chL = rlo >> 6, ulL = rlo & 63;
        int chH = rhi >> 6, ulH = rhi & 63;
        size_t tL = (size_t)(t0+rlo)*RR, tH = (size_t)(t0+rhi)*RR;
        #pragma unroll
        for (int ni = 0; ni < 6; ni++) {
            int c0 = wx*48 + ni*8 + 2*tig;
            float v0 = acc[mi][ni][0] + bcat[c0];
            float v1 = acc[mi][ni][1] + bcat[c0+1];
            float v2 = acc[mi][ni][2] + bcat[c0];
            float v3 = acc[mi][ni][3] + bcat[c0+1];
            if (c0 < 32) {
                v0 *= ksL; v1 *= ksL; v2 *= ksH; v3 *= ksH;
                *(uint32_t*)&g_Kb[tL + c0] = packbf(v0, v1);
                *(uint32_t*)&g_Kb[tH + c0] = packbf(v2, v3);
                KsT[(chL*32 + c0  )*72 + ulL] = __float2bfloat16(v0);
                KsT[(chL*32 + c0+1)*72 + ulL] = __float2bfloat16(v1);
                KsT[(chH*32 + c0  )*72 + ulH] = __float2bfloat16(v2);
                KsT[(chH*32 + c0+1)*72 + ulH] = __float2bfloat16(v3);
            } else if (c0 < 64) {
                int j0 = c0 - 32;
                __nv_bfloat16 b0 = __float2bfloat16(v0);
                __nv_bfloat16 b1 = __float2bfloat16(v1);
                __nv_bfloat16 b2 = __float2bfloat16(v2);
                __nv_bfloat16 b3 = __float2bfloat16(v3);
                VsT[(chL*32 + j0  )*72 + ulL] = b0;
                VsT[(chL*32 + j0+1)*72 + ulL] = b1;
                VsT[(chH*32 + j0  )*72 + ulH] = b2;
                VsT[(chH*32 + j0+1)*72 + ulH] = b3;
                size_t vbL = (size_t)(blockIdx.x*2 + chL)*2048;
                size_t vbH = (size_t)(blockIdx.x*2 + chH)*2048;
                g_VTb[vbL + (j0  )*64 + ulL] = b0;
                g_VTb[vbL + (j0+1)*64 + ulL] = b1;
                g_VTb[vbH + (j0  )*64 + ulH] = b2;
                g_VTb[vbH + (j0+1)*64 + ulH] = b3;
            } else {
                int r0 = c0 - 64;
                *(uint32_t*)&g_Qb[tL + r0] = packbf(v0*lamL, v1*lamL);
                *(uint32_t*)&g_Qb[tH + r0] = packbf(v2*lamH, v3*lamH);
            }
        }
    }
    __syncthreads();

    // B^T = (K~^T V)^T via MMA: per chunk 4 warps, warp tile m16 x n16, k=64
    {
        int ch = w >> 2, wl = w & 3;
        int wy2 = wl >> 1, wx2 = wl & 1;
        const __nv_bfloat16* Kt = KsT + ch*32*72;
        const __nv_bfloat16* Vt = VsT + ch*32*72;
        float accB[2][4];
        #pragma unroll
        for (int ni = 0; ni < 2; ni++)
            #pragma unroll
            for (int r = 0; r < 4; r++) accB[ni][r] = 0.f;
        #pragma unroll
        for (int ks = 0; ks < 4; ks++) {
            int kb = ks * 16;
            int rb = wy2 * 16;
            uint32_t a[4];
            a[0] = *(const uint32_t*)&Kt[(rb+g  )*72 + kb +     2*tig];
            a[1] = *(const uint32_t*)&Kt[(rb+8+g)*72 + kb +     2*tig];
            a[2] = *(const uint32_t*)&Kt[(rb+g  )*72 + kb + 8 + 2*tig];
            a[3] = *(const uint32_t*)&Kt[(rb+8+g)*72 + kb + 8 + 2*tig];
            #pragma unroll
            for (int ni = 0; ni < 2; ni++) {
                int nb = wx2*16 + ni*8;
                uint32_t b[2];
                b[0] = *(const uint32_t*)&Vt[(nb+g)*72 + kb +     2*tig];
                b[1] = *(const uint32_t*)&Vt[(nb+g)*72 + kb + 8 + 2*tig];
                mma16816(accB[ni], a, b);
            }
        }
        int cg = blockIdx.x*2 + ch;
        size_t base = (size_t)cg * 1024;
        #pragma unroll
        for (int ni = 0; ni < 2; ni++) {
            int i0 = wy2*16 + g, i1 = i0 + 8;
            int j0 = wx2*16 + ni*8 + 2*tig;
            g_BT[base + (j0  )*32 + i0] = accB[ni][0];
            g_BT[base + (j0+1)*32 + i0] = accB[ni][1];
            g_BT[base + (j0  )*32 + i1] = accB[ni][2];
            g_BT[base + (j0+1)*32 + i1] = accB[ni][3];
        }
        if (wl == 0 && lane == 0) g_gm[cg] = Lam[ch*64 + 63];
    }
}

// ---------------------------------------------------------------------------
// Kernel 2: scan over 1024 chunks (transposed layout, elementwise identical)
// ---------------------------------------------------------------------------
__global__ __launch_bounds__(32, 1) void k_scan()
{
    __shared__ float gs[NCK];
    const int e = blockIdx.x * 32 + threadIdx.x;
    for (int i = threadIdx.x; i < NCK; i += 32) gs[i] = g_gm[i];
    __syncthreads();
    float s = 0.f;
    #pragma unroll 8
    for (int c = 0; c < NCK; c++) {
        g_SpT[(size_t)c*1024 + e] = s;
        float gv = gs[c];
        s = fmaf(gv, s, gv * g_BT[(size_t)c*1024 + e]);
    }
}

// ---------------------------------------------------------------------------
// Kernel 3: 2 chunks/block, all-MMA, register-chained (one __syncthreads)
// A = tril(Q~K~^T) -> O = Q~S^T + A V -> head O Wo^T -> 1+tanh
// ---------------------------------------------------------------------------
__global__ __launch_bounds__(256, 2) void k_out(
    const float* __restrict__ Wo, const float* __restrict__ bo,
    float* __restrict__ out)
{
    __shared__ __align__(16) __nv_bfloat16 sQ [2*64*40];
    __shared__ __align__(16) __nv_bfloat16 sK [2*64*40];
    __shared__ __align__(16) __nv_bfloat16 sVT[2*32*72];
    __shared__ __align__(16) __nv_bfloat16 sST[2*32*40];
    __shared__ __align__(16) __nv_bfloat16 sWo[56*40];
    __shared__ float sbo[56];

    const int tid = threadIdx.x;
    const int cg0 = blockIdx.x * 2;

    // Stage Q, K (bf16 gmem, 64x32 per chunk)
    #pragma unroll
    for (int r = 0; r < 4; r++) {
        int slot = tid + 256*r;                 // 1024 = 2ch x 512
        int ch = slot >> 9, s = slot & 511;
        int row = s >> 3, c4 = (s & 7) << 2;
        size_t gi = ((size_t)(cg0+ch)*64 + row)*RR + c4;
        *(uint2*)&sQ[(ch*64+row)*40 + c4] = *(const uint2*)&g_Qb[gi];
        *(uint2*)&sK[(ch*64+row)*40 + c4] = *(const uint2*)&g_Kb[gi];
    }
    // Stage V^T (32x64 per chunk)
    #pragma unroll
    for (int r = 0; r < 4; r++) {
        int slot = tid + 256*r;
        int ch = slot >> 9, s = slot & 511;
        int row = s >> 4, c4 = (s & 15) << 2;
        *(uint2*)&sVT[(ch*32+row)*72 + c4] =
            *(const uint2*)&g_VTb[(size_t)(cg0+ch)*2048 + row*64 + c4];
    }
    // Stage S^T (fp32 -> bf16, 32x32 per chunk)
    #pragma unroll
    for (int r = 0; r < 2; r++) {
        int slot = tid + 256*r;
        int ch = slot >> 8, s = slot & 255;
        int row = s >> 3, c4 = (s & 7) << 2;
        float4 f = *(const float4*)&g_SpT[(size_t)(cg0+ch)*1024 + row*32 + c4];
        uint2 p; p.x = packbf(f.x, f.y); p.y = packbf(f.z, f.w);
        *(uint2*)&sST[(ch*32+row)*40 + c4] = p;
    }
    // Stage Wo (fp32 -> bf16, zero-padded to 56 rows)
    #pragma unroll
    for (int r = 0; r < 7; r++) {
        int idx = tid + 256*r;                  // 1792 = 56*32
        int m = idx >> 5, j = idx & 31;
        sWo[m*40 + j] = __float2bfloat16(m < MM ? Wo[m*RR + j] : 0.f);
    }
    if (tid < 56) sbo[tid] = (tid < MM) ? bo[tid] : 0.f;
    __syncthreads();

    const int lane = tid & 31, w = tid >> 5;
    const int g = lane >> 2, tig = lane & 3;
    const int ch = w >> 2, wr = w & 3;          // 4 warps per chunk, 16 rows each
    const __nv_bfloat16* Q  = sQ  + ch*64*40;
    const __nv_bfloat16* K  = sK  + ch*64*40;
    const __nv_bfloat16* VT = sVT + ch*32*72;
    const __nv_bfloat16* ST = sST + ch*32*40;
    const int rb = wr * 16;

    // Phase A: A = Q~ K~^T  (m16 x n64, k=32)
    uint32_t aq[2][4];
    float accA[8][4];
    #pragma unroll
    for (int ni = 0; ni < 8; ni++)
        #pragma unroll
        for (int r = 0; r < 4; r++) accA[ni][r] = 0.f;
    #pragma unroll
    for (int ks = 0; ks < 2; ks++) {
        int kb = ks * 16;
        aq[ks][0] = *(const uint32_t*)&Q[(rb+g  )*40 + kb +     2*tig];
        aq[ks][1] = *(const uint32_t*)&Q[(rb+8+g)*40 + kb +     2*tig];
        aq[ks][2] = *(const uint32_t*)&Q[(rb+g  )*40 + kb + 8 + 2*tig];
        aq[ks][3] = *(const uint32_t*)&Q[(rb+8+g)*40 + kb + 8 + 2*tig];
        #pragma unroll
        for (int ni = 0; ni < 8; ni++) {
            uint32_t b[2];
            b[0] = *(const uint32_t*)&K[(ni*8+g)*40 + kb +     2*tig];
            b[1] = *(const uint32_t*)&K[(ni*8+g)*40 + kb + 8 + 2*tig];
            mma16816(accA[ni], aq[ks], b);
        }
    }
    // tril mask + cvt: C-frag layout == A-frag layout of the next MMA
    uint32_t aA[4][4];
    {
        int ulo = rb + g, uhi = rb + g + 8;
        #pragma unroll
        for (int ni = 0; ni < 8; ni++) {
            int s0 = ni*8 + 2*tig, s1 = s0 + 1;
            float m0 = (s0 <= ulo) ? accA[ni][0] : 0.f;
            float m1 = (s1 <= ulo) ? accA[ni][1] : 0.f;
            float m2 = (s0 <= uhi) ? accA[ni][2] : 0.f;
            float m3 = (s1 <= uhi) ? accA[ni][3] : 0.f;
            int ks2 = ni >> 1;
            if ((ni & 1) == 0) { aA[ks2][0] = packbf(m0, m1); aA[ks2][1] = packbf(m2, m3); }
            else               { aA[ks2][2] = packbf(m0, m1); aA[ks2][3] = packbf(m2, m3); }
        }
    }
    // Phase O: O = Q~ S^T-form + A V   (m16 x n32)
    float accO[4][4];
    #pragma unroll
    for (int ni = 0; ni < 4; ni++)
        #pragma unroll
        for (int r = 0; r < 4; r++) accO[ni][r] = 0.f;
    #pragma unroll
    for (int ks = 0; ks < 2; ks++) {
        int kb = ks * 16;
        #pragma unroll
        for (int ni = 0; ni < 4; ni++) {
            uint32_t b[2];
            b[0] = *(const uint32_t*)&ST[(ni*8+g)*40 + kb +     2*tig];
            b[1] = *(const uint32_t*)&ST[(ni*8+g)*40 + kb + 8 + 2*tig];
            mma16816(accO[ni], aq[ks], b);
        }
    }
    #pragma unroll
    for (int ks = 0; ks < 4; ks++) {
        int kb = ks * 16;
        #pragma unroll
        for (int ni = 0; ni < 4; ni++) {
            uint32_t b[2];
            b[0] = *(const uint32_t*)&VT[(ni*8+g)*72 + kb +     2*tig];
            b[1] = *(const uint32_t*)&VT[(ni*8+g)*72 + kb + 8 + 2*tig];
            mma16816(accO[ni], aA[ks], b);
        }
    }
    // cvt O -> A-frags
    uint32_t aO[2][4];
    #pragma unroll
    for (int ks2 = 0; ks2 < 2; ks2++) {
        aO[ks2][0] = packbf(accO[2*ks2  ][0], accO[2*ks2  ][1]);
        aO[ks2][1] = packbf(accO[2*ks2  ][2], accO[2*ks2  ][3]);
        aO[ks2][2] = packbf(accO[2*ks2+1][0], accO[2*ks2+1][1]);
        aO[ks2][3] = packbf(accO[2*ks2+1][2], accO[2*ks2+1][3]);
    }
    // Head: raw = O Wo^T  (m16 x n56, k=32)
    float accH[7][4];
    #pragma unroll
    for (int ni = 0; ni < 7; ni++)
        #pragma unroll
        for (int r = 0; r < 4; r++) accH[ni][r] = 0.f;
    #pragma unroll
    for (int ks = 0; ks < 2; ks++) {
        int kb = ks * 16;
        #pragma unroll
        for (int ni = 0; ni < 7; ni++) {
            uint32_t b[2];
            b[0] = *(const uint32_t*)&sWo[(ni*8+g)*40 + kb +     2*tig];
            b[1] = *(const uint32_t*)&sWo[(ni*8+g)*40 + kb + 8 + 2*tig];
            mma16816(accH[ni], aO[ks], b);
        }
    }
    // Epilogue
    {
        size_t t0c = (size_t)(cg0 + ch) * 64;
        size_t rl = (t0c + rb + g) * MM;
        size_t rh = (t0c + rb + g + 8) * MM;
        #pragma unroll
        for (int ni = 0; ni < 7; ni++) {
            int m0 = ni*8 + 2*tig, m1 = m0 + 1;
            if (m0 < MM) {
                out[rl + m0] = 1.f + tanh_fast(accH[ni][0] + sbo[m0]);
                out[rh + m0] = 1.f + tanh_fast(accH[ni][2] + sbo[m0]);
            }
            if (m1 < MM) {
                out[rl + m1] = 1.f + tanh_fast(accH[ni][1] + sbo[m1]);
                out[rh + m1] = 1.f + tanh_fast(accH[ni][3] + sbo[m1]);
            }
        }
    }
}

// ---------------------------------------------------------------------------
extern "C" void kernel_launch(void* const* d_in, const int* in_sizes, int n_in,
                              void* d_out, int out_size)
{
    const float* X  = (const float*)d_in[0];
    const float* lr = (const float*)d_in[1];
    const float* dc = (const float*)d_in[2];
    const float* Wk = (const float*)d_in[3];
    const float* bk = (const float*)d_in[4];
    const float* Wv = (const float*)d_in[5];
    const float* bv = (const float*)d_in[6];
    const float* Wq = (const float*)d_in[7];
    const float* bq = (const float*)d_in[8];
    const float* Wo = (const float*)d_in[9];
    const float* bo = (const float*)d_in[10];
    float* out = (float*)d_out;

    k_proj<<<NCK/2, 256>>>(X, lr, dc, Wk, bk, Wv, bv, Wq, bq);
    k_scan<<<32, 32>>>();
    k_out<<<NCK/2, 256>>>(Wo, bo, out);
    (void)in_sizes; (void)n_in; (void)out_size;
}

// round 4
// speedup vs baseline: 7.1516x; 5.9628x over previous
#include <cuda_runtime.h>
#include <cuda_bf16.h>
#include <math.h>
#include <stdint.h>

#define TT 65536
#define DD 256
#define RR 32
#define MM 52
#define CC 64
#define NCK 1024
#define SEG 16
#define NSEG (NCK/SEG)   // 64

// Scratch (device globals; no allocation allowed)
__device__ __align__(16) __nv_bfloat16 g_Qb [TT*RR];   // Lambda_u * q_u   [t][r]
__device__ __align__(16) __nv_bfloat16 g_Kb [TT*RR];   // (l/Lambda)*k     [t][r]
__device__ __align__(16) __nv_bfloat16 g_VTb[TT*RR];   // per-chunk V^T    [chunk][j=32][u=64]
__device__ __align__(16) float g_BT [NCK*RR*RR];       // per-chunk (K~^T V)^T  [chunk][j][i]
__device__ float g_gm[NCK];                            // per-chunk Lambda_C
__device__ __align__(16) float g_SpT[NCK*RR*RR];       // state^T BEFORE each chunk
__device__ __align__(16) float g_carry[NSEG*1024];     // segment-local carries
__device__ __align__(16) float g_P   [NSEG*1024];      // incoming state per segment

__device__ __forceinline__ uint32_t packbf(float a, float b) {
    __nv_bfloat162 h = __floats2bfloat162_rn(a, b);
    return *reinterpret_cast<uint32_t*>(&h);
}
__device__ __forceinline__ float tanh_fast(float x) {
    float y; asm("tanh.approx.f32 %0, %1;" : "=f"(y) : "f"(x)); return y;
}
__device__ __forceinline__ void mma16816(float* c, const uint32_t* a, const uint32_t* b) {
    asm volatile("mma.sync.aligned.m16n8k16.row.col.f32.bf16.bf16.f32 "
        "{%0,%1,%2,%3}, {%4,%5,%6,%7}, {%8,%9}, {%0,%1,%2,%3};"
        : "+f"(c[0]), "+f"(c[1]), "+f"(c[2]), "+f"(c[3])
        : "r"(a[0]), "r"(a[1]), "r"(a[2]), "r"(a[3]), "r"(b[0]), "r"(b[1]));
}

// ---------------------------------------------------------------------------
// Kernel 1: 2 chunks (128 rows) per block. bf16 MMA projections + B + gamma
// ---------------------------------------------------------------------------
__global__ __launch_bounds__(256, 2) void k_proj(
    const float* __restrict__ X,  const float* __restrict__ lr,
    const float* __restrict__ dec,
    const float* __restrict__ Wk, const float* __restrict__ bk,
    const float* __restrict__ Wv, const float* __restrict__ bv,
    const float* __restrict__ Wq, const float* __restrict__ bq)
{
    __shared__ __align__(16) __nv_bfloat16 sXs[128*72];   // X tile (also KsT/VsT later)
    __shared__ __align__(16) __nv_bfloat16 sWs[96*72];    // W tile (Wk|Wv|Wq)
    __shared__ float Lam[128], Lrs[128], Dcs[128], bcat[96];

    const int tid  = threadIdx.x;
    const int lane = tid & 31, w = tid >> 5;
    const int g = lane >> 2, tig = lane & 3;
    const int t0 = blockIdx.x * 128;

    if (tid < 96)
        bcat[tid] = (tid < 32) ? bk[tid] : (tid < 64 ? bv[tid-32] : bq[tid-64]);
    if (tid < 128) Lrs[tid] = lr[t0 + tid];
    else           Dcs[tid-128] = dec[t0 + tid - 128];
    __syncthreads();
    if (tid < 2) {
        float p = 1.f;
        #pragma unroll
        for (int u = 0; u < 64; u++) { p *= (1.f - Dcs[64*tid + u]); Lam[64*tid + u] = p; }
    }

    const int wy = w >> 1, wx = w & 1;   // warp tile: 32 rows x 48 cols
    float acc[2][6][4];
    #pragma unroll
    for (int mi = 0; mi < 2; mi++)
        #pragma unroll
        for (int ni = 0; ni < 6; ni++)
            #pragma unroll
            for (int r = 0; r < 4; r++) acc[mi][ni][r] = 0.f;

    for (int kk0 = 0; kk0 < DD; kk0 += 64) {
        // Stage X tile 128x64 (f32 -> bf16), 8 float4 per thread
        #pragma unroll
        for (int r = 0; r < 8; r++) {
            int slot = tid + 256*r;
            int row = slot >> 4, k4 = (slot & 15) << 2;
            float4 x4 = *(const float4*)&X[(size_t)(t0+row)*DD + kk0 + k4];
            uint2 p; p.x = packbf(x4.x, x4.y); p.y = packbf(x4.z, x4.w);
            *(uint2*)&sXs[row*72 + k4] = p;
        }
        // Stage W tile 96x64
        #pragma unroll
        for (int r = 0; r < 6; r++) {
            int slot = tid + 256*r;
            int row = slot >> 4, k4 = (slot & 15) << 2;
            const float* Wsrc = (row < 32) ? Wk : (row < 64 ? Wv : Wq);
            float4 w4 = *(const float4*)&Wsrc[(row & 31)*DD + kk0 + k4];
            uint2 p; p.x = packbf(w4.x, w4.y); p.y = packbf(w4.z, w4.w);
            *(uint2*)&sWs[row*72 + k4] = p;
        }
        __syncthreads();
        #pragma unroll
        for (int ks = 0; ks < 4; ks++) {
            int kb = ks * 16;
            uint32_t a[2][4];
            #pragma unroll
            for (int mi = 0; mi < 2; mi++) {
                int rb = wy*32 + mi*16;
                a[mi][0] = *(const uint32_t*)&sXs[(rb+g  )*72 + kb +     2*tig];
                a[mi][1] = *(const uint32_t*)&sXs[(rb+8+g)*72 + kb +     2*tig];
                a[mi][2] = *(const uint32_t*)&sXs[(rb+g  )*72 + kb + 8 + 2*tig];
                a[mi][3] = *(const uint32_t*)&sXs[(rb+8+g)*72 + kb + 8 + 2*tig];
            }
            #pragma unroll
            for (int ni = 0; ni < 6; ni++) {
                int nb = wx*48 + ni*8;
                uint32_t b[2];
                b[0] = *(const uint32_t*)&sWs[(nb+g)*72 + kb +     2*tig];
                b[1] = *(const uint32_t*)&sWs[(nb+g)*72 + kb + 8 + 2*tig];
                mma16816(acc[0][ni], a[0], b);
                mma16816(acc[1][ni], a[1], b);
            }
        }
        __syncthreads();
    }

    // Epilogue: scale + write K~/V^T/Q~; KsT/VsT alias sXs (all reads done)
    __nv_bfloat16* KsT = sXs;              // [2][32][72]  K~^T per chunk
    __nv_bfloat16* VsT = sXs + 2*32*72;    // [2][32][72]  V^T per chunk
    #pragma unroll
    for (int mi = 0; mi < 2; mi++) {
        int rlo = wy*32 + mi*16 + g, rhi = rlo + 8;
        float lamL = Lam[rlo], lamH = Lam[rhi];
        float ksL = Lrs[rlo]/lamL, ksH = Lrs[rhi]/lamH;
        int chL = rlo >> 6, ulL = rlo & 63;
        int chH = rhi >> 6, ulH = rhi & 63;
        size_t tL = (size_t)(t0+rlo)*RR, tH = (size_t)(t0+rhi)*RR;
        #pragma unroll
        for (int ni = 0; ni < 6; ni++) {
            int c0 = wx*48 + ni*8 + 2*tig;
            float v0 = acc[mi][ni][0] + bcat[c0];
            float v1 = acc[mi][ni][1] + bcat[c0+1];
            float v2 = acc[mi][ni][2] + bcat[c0];
            float v3 = acc[mi][ni][3] + bcat[c0+1];
            if (c0 < 32) {
                v0 *= ksL; v1 *= ksL; v2 *= ksH; v3 *= ksH;
                *(uint32_t*)&g_Kb[tL + c0] = packbf(v0, v1);
                *(uint32_t*)&g_Kb[tH + c0] = packbf(v2, v3);
                KsT[(chL*32 + c0  )*72 + ulL] = __float2bfloat16(v0);
                KsT[(chL*32 + c0+1)*72 + ulL] = __float2bfloat16(v1);
                KsT[(chH*32 + c0  )*72 + ulH] = __float2bfloat16(v2);
                KsT[(chH*32 + c0+1)*72 + ulH] = __float2bfloat16(v3);
            } else if (c0 < 64) {
                int j0 = c0 - 32;
                __nv_bfloat16 b0 = __float2bfloat16(v0);
                __nv_bfloat16 b1 = __float2bfloat16(v1);
                __nv_bfloat16 b2 = __float2bfloat16(v2);
                __nv_bfloat16 b3 = __float2bfloat16(v3);
                VsT[(chL*32 + j0  )*72 + ulL] = b0;
                VsT[(chL*32 + j0+1)*72 + ulL] = b1;
                VsT[(chH*32 + j0  )*72 + ulH] = b2;
                VsT[(chH*32 + j0+1)*72 + ulH] = b3;
                size_t vbL = (size_t)(blockIdx.x*2 + chL)*2048;
                size_t vbH = (size_t)(blockIdx.x*2 + chH)*2048;
                g_VTb[vbL + (j0  )*64 + ulL] = b0;
                g_VTb[vbL + (j0+1)*64 + ulL] = b1;
                g_VTb[vbH + (j0  )*64 + ulH] = b2;
                g_VTb[vbH + (j0+1)*64 + ulH] = b3;
            } else {
                int r0 = c0 - 64;
                *(uint32_t*)&g_Qb[tL + r0] = packbf(v0*lamL, v1*lamL);
                *(uint32_t*)&g_Qb[tH + r0] = packbf(v2*lamH, v3*lamH);
            }
        }
    }
    __syncthreads();

    // B^T = (K~^T V)^T via MMA: per chunk 4 warps, warp tile m16 x n16, k=64
    {
        int ch = w >> 2, wl = w & 3;
        int wy2 = wl >> 1, wx2 = wl & 1;
        const __nv_bfloat16* Kt = KsT + ch*32*72;
        const __nv_bfloat16* Vt = VsT + ch*32*72;
        float accB[2][4];
        #pragma unroll
        for (int ni = 0; ni < 2; ni++)
            #pragma unroll
            for (int r = 0; r < 4; r++) accB[ni][r] = 0.f;
        #pragma unroll
        for (int ks = 0; ks < 4; ks++) {
            int kb = ks * 16;
            int rb = wy2 * 16;
            uint32_t a[4];
            a[0] = *(const uint32_t*)&Kt[(rb+g  )*72 + kb +     2*tig];
            a[1] = *(const uint32_t*)&Kt[(rb+8+g)*72 + kb +     2*tig];
            a[2] = *(const uint32_t*)&Kt[(rb+g  )*72 + kb + 8 + 2*tig];
            a[3] = *(const uint32_t*)&Kt[(rb+8+g)*72 + kb + 8 + 2*tig];
            #pragma unroll
            for (int ni = 0; ni < 2; ni++) {
                int nb = wx2*16 + ni*8;
                uint32_t b[2];
                b[0] = *(const uint32_t*)&Vt[(nb+g)*72 + kb +     2*tig];
                b[1] = *(const uint32_t*)&Vt[(nb+g)*72 + kb + 8 + 2*tig];
                mma16816(accB[ni], a, b);
            }
        }
        int cg = blockIdx.x*2 + ch;
        size_t base = (size_t)cg * 1024;
        #pragma unroll
        for (int ni = 0; ni < 2; ni++) {
            int i0 = wy2*16 + g, i1 = i0 + 8;
            int j0 = wx2*16 + ni*8 + 2*tig;
            g_BT[base + (j0  )*32 + i0] = accB[ni][0];
            g_BT[base + (j0+1)*32 + i0] = accB[ni][1];
            g_BT[base + (j0  )*32 + i1] = accB[ni][2];
            g_BT[base + (j0+1)*32 + i1] = accB[ni][3];
        }
        if (wl == 0 && lane == 0) g_gm[cg] = Lam[ch*64 + 63];
    }
}

// ---------------------------------------------------------------------------
// Hierarchical scan: S_c = gamma_c (S_{c-1} + B_c), serial depth 16+64+16.
// Phase 1: per-segment local carry (zero init).
// ---------------------------------------------------------------------------
__global__ __launch_bounds__(1024, 1) void k_scan1()
{
    __shared__ float gs[SEG];
    const int b = blockIdx.x, e = threadIdx.x;
    if (e < SEG) gs[e] = g_gm[b*SEG + e];
    __syncthreads();
    const float* Bp = g_BT + (size_t)b*SEG*1024 + e;
    float bvv[SEG];
    #pragma unroll
    for (int c = 0; c < SEG; c++) bvv[c] = Bp[(size_t)c*1024];
    float s = 0.f;
    #pragma unroll
    for (int c = 0; c < SEG; c++) s = gs[c] * (s + bvv[c]);
    g_carry[(size_t)b*1024 + e] = s;
}

// Phase 2: scan 64 segment carries (single block, loads prefetched by 16)
__global__ __launch_bounds__(1024, 1) void k_scan2()
{
    __shared__ float As[NSEG];
    const int e = threadIdx.x;
    if (e < NSEG) {
        float p = 1.f;
        #pragma unroll
        for (int c = 0; c < SEG; c++) p *= g_gm[e*SEG + c];
        As[e] = p;
    }
    __syncthreads();
    float p = 0.f;
    for (int bb = 0; bb < NSEG; bb += 16) {
        float cv[16];
        #pragma unroll
        for (int j = 0; j < 16; j++) cv[j] = g_carry[(size_t)(bb+j)*1024 + e];
        #pragma unroll
        for (int j = 0; j < 16; j++) {
            g_P[(size_t)(bb+j)*1024 + e] = p;
            p = fmaf(As[bb+j], p, cv[j]);
        }
    }
}

// Phase 3: replay each segment with true incoming state, emit g_SpT
__global__ __launch_bounds__(1024, 1) void k_scan3()
{
    __shared__ float gs[SEG];
    const int b = blockIdx.x, e = threadIdx.x;
    if (e < SEG) gs[e] = g_gm[b*SEG + e];
    __syncthreads();
    const float* Bp = g_BT + (size_t)b*SEG*1024 + e;
    float bvv[SEG];
    #pragma unroll
    for (int c = 0; c < SEG; c++) bvv[c] = Bp[(size_t)c*1024];
    float s = g_P[(size_t)b*1024 + e];
    float* Sp = g_SpT + (size_t)b*SEG*1024 + e;
    #pragma unroll
    for (int c = 0; c < SEG; c++) {
        Sp[(size_t)c*1024] = s;
        s = gs[c] * (s + bvv[c]);
    }
}

// ---------------------------------------------------------------------------
// Kernel 3: 2 chunks/block, all-MMA, register-chained (one __syncthreads)
// ---------------------------------------------------------------------------
__global__ __launch_bounds__(256, 2) void k_out(
    const float* __restrict__ Wo, const float* __restrict__ bo,
    float* __restrict__ out)
{
    __shared__ __align__(16) __nv_bfloat16 sQ [2*64*40];
    __shared__ __align__(16) __nv_bfloat16 sK [2*64*40];
    __shared__ __align__(16) __nv_bfloat16 sVT[2*32*72];
    __shared__ __align__(16) __nv_bfloat16 sST[2*32*40];
    __shared__ __align__(16) __nv_bfloat16 sWo[56*40];
    __shared__ float sbo[56];

    const int tid = threadIdx.x;
    const int cg0 = blockIdx.x * 2;

    #pragma unroll
    for (int r = 0; r < 4; r++) {
        int slot = tid + 256*r;
        int ch = slot >> 9, s = slot & 511;
        int row = s >> 3, c4 = (s & 7) << 2;
        size_t gi = ((size_t)(cg0+ch)*64 + row)*RR + c4;
        *(uint2*)&sQ[(ch*64+row)*40 + c4] = *(const uint2*)&g_Qb[gi];
        *(uint2*)&sK[(ch*64+row)*40 + c4] = *(const uint2*)&g_Kb[gi];
    }
    #pragma unroll
    for (int r = 0; r < 4; r++) {
        int slot = tid + 256*r;
        int ch = slot >> 9, s = slot & 511;
        int row = s >> 4, c4 = (s & 15) << 2;
        *(uint2*)&sVT[(ch*32+row)*72 + c4] =
            *(const uint2*)&g_VTb[(size_t)(cg0+ch)*2048 + row*64 + c4];
    }
    #pragma unroll
    for (int r = 0; r < 2; r++) {
        int slot = tid + 256*r;
        int ch = slot >> 8, s = slot & 255;
        int row = s >> 3, c4 = (s & 7) << 2;
        float4 f = *(const float4*)&g_SpT[(size_t)(cg0+ch)*1024 + row*32 + c4];
        uint2 p; p.x = packbf(f.x, f.y); p.y = packbf(f.z, f.w);
        *(uint2*)&sST[(ch*32+row)*40 + c4] = p;
    }
    #pragma unroll
    for (int r = 0; r < 7; r++) {
        int idx = tid + 256*r;
        int m = idx >> 5, j = idx & 31;
        sWo[m*40 + j] = __float2bfloat16(m < MM ? Wo[m*RR + j] : 0.f);
    }
    if (tid < 56) sbo[tid] = (tid < MM) ? bo[tid] : 0.f;
    __syncthreads();

    const int lane = tid & 31, w = tid >> 5;
    const int g = lane >> 2, tig = lane & 3;
    const int ch = w >> 2, wr = w & 3;
    const __nv_bfloat16* Q  = sQ  + ch*64*40;
    const __nv_bfloat16* K  = sK  + ch*64*40;
    const __nv_bfloat16* VT = sVT + ch*32*72;
    const __nv_bfloat16* ST = sST + ch*32*40;
    const int rb = wr * 16;

    uint32_t aq[2][4];
    float accA[8][4];
    #pragma unroll
    for (int ni = 0; ni < 8; ni++)
        #pragma unroll
        for (int r = 0; r < 4; r++) accA[ni][r] = 0.f;
    #pragma unroll
    for (int ks = 0; ks < 2; ks++) {
        int kb = ks * 16;
        aq[ks][0] = *(const uint32_t*)&Q[(rb+g  )*40 + kb +     2*tig];
        aq[ks][1] = *(const uint32_t*)&Q[(rb+8+g)*40 + kb +     2*tig];
        aq[ks][2] = *(const uint32_t*)&Q[(rb+g  )*40 + kb + 8 + 2*tig];
        aq[ks][3] = *(const uint32_t*)&Q[(rb+8+g)*40 + kb + 8 + 2*tig];
        #pragma unroll
        for (int ni = 0; ni < 8; ni++) {
            uint32_t b[2];
            b[0] = *(const uint32_t*)&K[(ni*8+g)*40 + kb +     2*tig];
            b[1] = *(const uint32_t*)&K[(ni*8+g)*40 + kb + 8 + 2*tig];
            mma16816(accA[ni], aq[ks], b);
        }
    }
    uint32_t aA[4][4];
    {
        int ulo = rb + g, uhi = rb + g + 8;
        #pragma unroll
        for (int ni = 0; ni < 8; ni++) {
            int s0 = ni*8 + 2*tig, s1 = s0 + 1;
            float m0 = (s0 <= ulo) ? accA[ni][0] : 0.f;
            float m1 = (s1 <= ulo) ? accA[ni][1] : 0.f;
            float m2 = (s0 <= uhi) ? accA[ni][2] : 0.f;
            float m3 = (s1 <= uhi) ? accA[ni][3] : 0.f;
            int ks2 = ni >> 1;
            if ((ni & 1) == 0) { aA[ks2][0] = packbf(m0, m1); aA[ks2][1] = packbf(m2, m3); }
            else               { aA[ks2][2] = packbf(m0, m1); aA[ks2][3] = packbf(m2, m3); }
        }
    }
    float accO[4][4];
    #pragma unroll
    for (int ni = 0; ni < 4; ni++)
        #pragma unroll
        for (int r = 0; r < 4; r++) accO[ni][r] = 0.f;
    #pragma unroll
    for (int ks = 0; ks < 2; ks++) {
        int kb = ks * 16;
        #pragma unroll
        for (int ni = 0; ni < 4; ni++) {
            uint32_t b[2];
            b[0] = *(const uint32_t*)&ST[(ni*8+g)*40 + kb +     2*tig];
            b[1] = *(const uint32_t*)&ST[(ni*8+g)*40 + kb + 8 + 2*tig];
            mma16816(accO[ni], aq[ks], b);
        }
    }
    #pragma unroll
    for (int ks = 0; ks < 4; ks++) {
        int kb = ks * 16;
        #pragma unroll
        for (int ni = 0; ni < 4; ni++) {
            uint32_t b[2];
            b[0] = *(const uint32_t*)&VT[(ni*8+g)*72 + kb +     2*tig];
            b[1] = *(const uint32_t*)&VT[(ni*8+g)*72 + kb + 8 + 2*tig];
            mma16816(accO[ni], aA[ks], b);
        }
    }
    uint32_t aO[2][4];
    #pragma unroll
    for (int ks2 = 0; ks2 < 2; ks2++) {
        aO[ks2][0] = packbf(accO[2*ks2  ][0], accO[2*ks2  ][1]);
        aO[ks2][1] = packbf(accO[2*ks2  ][2], accO[2*ks2  ][3]);
        aO[ks2][2] = packbf(accO[2*ks2+1][0], accO[2*ks2+1][1]);
        aO[ks2][3] = packbf(accO[2*ks2+1][2], accO[2*ks2+1][3]);
    }
    float accH[7][4];
    #pragma unroll
    for (int ni = 0; ni < 7; ni++)
        #pragma unroll
        for (int r = 0; r < 4; r++) accH[ni][r] = 0.f;
    #pragma unroll
    for (int ks = 0; ks < 2; ks++) {
        int kb = ks * 16;
        #pragma unroll
        for (int ni = 0; ni < 7; ni++) {
            uint32_t b[2];
            b[0] = *(const uint32_t*)&sWo[(ni*8+g)*40 + kb +     2*tig];
            b[1] = *(const uint32_t*)&sWo[(ni*8+g)*40 + kb + 8 + 2*tig];
            mma16816(accH[ni], aO[ks], b);
        }
    }
    {
        size_t t0c = (size_t)(cg0 + ch) * 64;
        size_t rl = (t0c + rb + g) * MM;
        size_t rh = (t0c + rb + g + 8) * MM;
        #pragma unroll
        for (int ni = 0; ni < 7; ni++) {
            int m0 = ni*8 + 2*tig, m1 = m0 + 1;
            if (m0 < MM) {
                out[rl + m0] = 1.f + tanh_fast(accH[ni][0] + sbo[m0]);
                out[rh + m0] = 1.f + tanh_fast(accH[ni][2] + sbo[m0]);
            }
            if (m1 < MM) {
                out[rl + m1] = 1.f + tanh_fast(accH[ni][1] + sbo[m1]);
                out[rh + m1] = 1.f + tanh_fast(accH[ni][3] + sbo[m1]);
            }
        }
    }
}

// ---------------------------------------------------------------------------
extern "C" void kernel_launch(void* const* d_in, const int* in_sizes, int n_in,
                              void* d_out, int out_size)
{
    const float* X  = (const float*)d_in[0];
    const float* lr = (const float*)d_in[1];
    const float* dc = (const float*)d_in[2];
    const float* Wk = (const float*)d_in[3];
    const float* bk = (const float*)d_in[4];
    const float* Wv = (const float*)d_in[5];
    const float* bv = (const float*)d_in[6];
    const float* Wq = (const float*)d_in[7];
    const float* bq = (const float*)d_in[8];
    const float* Wo = (const float*)d_in[9];
    const float* bo = (const float*)d_in[10];
    float* out = (float*)d_out;

    k_proj<<<NCK/2, 256>>>(X, lr, dc, Wk, bk, Wv, bv, Wq, bq);
    k_scan1<<<NSEG, 1024>>>();
    k_scan2<<<1, 1024>>>();
    k_scan3<<<NSEG, 1024>>>();
    k_out<<<NCK/2, 256>>>(Wo, bo, out);
    (void)in_sizes; (void)n_in; (void)out_size;
}

// round 6
// speedup vs baseline: 9.0356x; 1.2634x over previous
#include <cuda_runtime.h>
#include <cuda_bf16.h>
#include <math.h>
#include <stdint.h>

#define TT 65536
#define DD 256
#define RR 32
#define MM 52
#define CC 64
#define NCK 1024
#define SEG 16
#define NSEG (NCK/SEG)   // 64

// Scratch (device globals; no allocation allowed)
__device__ __align__(16) __nv_bfloat16 g_Qb [TT*RR];   // Lambda_u * q_u   [t][r]
__device__ __align__(16) __nv_bfloat16 g_Kb [TT*RR];   // (l/Lambda)*k     [t][r]
__device__ __align__(16) __nv_bfloat16 g_VTb[TT*RR];   // per-chunk V^T    [chunk][j=32][u=64]
__device__ __align__(16) float g_BT [NCK*RR*RR];       // per-chunk (K~^T V)^T  [chunk][j][i]
__device__ float g_gm[NCK];                            // per-chunk Lambda_C
__device__ __align__(16) float g_SpT[NCK*RR*RR];       // state^T BEFORE each chunk
__device__ __align__(16) float g_carry[NSEG*1024];     // segment-local carries

__device__ __forceinline__ uint32_t packbf(float a, float b) {
    __nv_bfloat162 h = __floats2bfloat162_rn(a, b);
    return *reinterpret_cast<uint32_t*>(&h);
}
__device__ __forceinline__ float tanh_fast(float x) {
    float y; asm("tanh.approx.f32 %0, %1;" : "=f"(y) : "f"(x)); return y;
}
__device__ __forceinline__ void mma16816(float* c, const uint32_t* a, const uint32_t* b) {
    asm volatile("mma.sync.aligned.m16n8k16.row.col.f32.bf16.bf16.f32 "
        "{%0,%1,%2,%3}, {%4,%5,%6,%7}, {%8,%9}, {%0,%1,%2,%3};"
        : "+f"(c[0]), "+f"(c[1]), "+f"(c[2]), "+f"(c[3])
        : "r"(a[0]), "r"(a[1]), "r"(a[2]), "r"(a[3]), "r"(b[0]), "r"(b[1]));
}

// ---------------------------------------------------------------------------
// Kernel 1: 2 chunks (128 rows) per block. bf16 MMA projections + B + gamma.
// W preloaded once (96x256 bf16); X software-pipelined via register prefetch.
// ---------------------------------------------------------------------------
__global__ __launch_bounds__(256, 2) void k_proj(
    const float* __restrict__ X,  const float* __restrict__ lr,
    const float* __restrict__ dec,
    const float* __restrict__ Wk, const float* __restrict__ bk,
    const float* __restrict__ Wv, const float* __restrict__ bv,
    const float* __restrict__ Wq, const float* __restrict__ bq)
{
    extern __shared__ __align__(16) __nv_bfloat16 dsm[];
    __nv_bfloat16* sW = dsm;                 // 96 x 264  (full K=256 + pad 8)
    __nv_bfloat16* sX = dsm + 96*264;        // 128 x 72  (one 64-col k-slab)
    __shared__ float Lam[128], Lrs[128], Dcs[128], bcat[96];

    const int tid  = threadIdx.x;
    const int lane = tid & 31, w = tid >> 5;
    const int g = lane >> 2, tig = lane & 3;
    const int t0 = blockIdx.x * 128;

    if (tid < 96)
        bcat[tid] = (tid < 32) ? bk[tid] : (tid < 64 ? bv[tid-32] : bq[tid-64]);
    if (tid < 128) Lrs[tid] = lr[t0 + tid];
    else           Dcs[tid-128] = dec[t0 + tid - 128];

    // Prefetch X slab 0 into registers (8 float4 per thread)
    float4 R[8];
    #pragma unroll
    for (int r = 0; r < 8; r++) {
        int slot = tid + 256*r;
        int row = slot >> 4, k4 = (slot & 15) << 2;
        R[r] = *(const float4*)&X[(size_t)(t0+row)*DD + k4];
    }

    // Preload full W (96x256 f32 -> bf16), 24 float4 per thread
    #pragma unroll
    for (int r = 0; r < 24; r++) {
        int slot = tid + 256*r;                  // 6144 slots
        int row = slot >> 6, k4 = (slot & 63) << 2;
        const float* Wsrc = (row < 32) ? Wk : (row < 64 ? Wv : Wq);
        float4 w4 = *(const float4*)&Wsrc[(row & 31)*DD + k4];
        uint2 p; p.x = packbf(w4.x, w4.y); p.y = packbf(w4.z, w4.w);
        *(uint2*)&sW[row*264 + k4] = p;
    }

    __syncthreads();           // Dcs visible
    if (tid < 2) {
        float p = 1.f;
        #pragma unroll
        for (int u = 0; u < 64; u++) { p *= (1.f - Dcs[64*tid + u]); Lam[64*tid + u] = p; }
    }

    // Store X slab 0
    #pragma unroll
    for (int r = 0; r < 8; r++) {
        int slot = tid + 256*r;
        int row = slot >> 4, k4 = (slot & 15) << 2;
        uint2 p; p.x = packbf(R[r].x, R[r].y); p.y = packbf(R[r].z, R[r].w);
        *(uint2*)&sX[row*72 + k4] = p;
    }
    __syncthreads();           // X slab 0 + W + Lam all visible

    const int wy = w >> 1, wx = w & 1;   // warp tile: 32 rows x 48 cols
    float acc[2][6][4];
    #pragma unroll
    for (int mi = 0; mi < 2; mi++)
        #pragma unroll
        for (int ni = 0; ni < 6; ni++)
            #pragma unroll
            for (int r = 0; r < 4; r++) acc[mi][ni][r] = 0.f;

    #pragma unroll
    for (int it = 0; it < 4; it++) {
        // Prefetch next X slab (LDG in flight during MMA section)
        if (it < 3) {
            int kk0n = (it+1) * 64;
            #pragma unroll
            for (int r = 0; r < 8; r++) {
                int slot = tid + 256*r;
                int row = slot >> 4, k4 = (slot & 15) << 2;
                R[r] = *(const float4*)&X[(size_t)(t0+row)*DD + kk0n + k4];
            }
        }
        // MMA over current slab
        #pragma unroll
        for (int ks = 0; ks < 4; ks++) {
            int kbX = ks * 16;
            int kbW = it * 64 + ks * 16;
            uint32_t a[2][4];
            #pragma unroll
            for (int mi = 0; mi < 2; mi++) {
                int rb = wy*32 + mi*16;
                a[mi][0] = *(const uint32_t*)&sX[(rb+g  )*72 + kbX +     2*tig];
                a[mi][1] = *(const uint32_t*)&sX[(rb+8+g)*72 + kbX +     2*tig];
                a[mi][2] = *(const uint32_t*)&sX[(rb+g  )*72 + kbX + 8 + 2*tig];
                a[mi][3] = *(const uint32_t*)&sX[(rb+8+g)*72 + kbX + 8 + 2*tig];
            }
            #pragma unroll
            for (int ni = 0; ni < 6; ni++) {
                int nb = wx*48 + ni*8;
                uint32_t b[2];
                b[0] = *(const uint32_t*)&sW[(nb+g)*264 + kbW +     2*tig];
                b[1] = *(const uint32_t*)&sW[(nb+g)*264 + kbW + 8 + 2*tig];
                mma16816(acc[0][ni], a[0], b);
                mma16816(acc[1][ni], a[1], b);
            }
        }
        if (it < 3) {
            __syncthreads();   // all warps done reading sX
            #pragma unroll
            for (int r = 0; r < 8; r++) {
                int slot = tid + 256*r;
                int row = slot >> 4, k4 = (slot & 15) << 2;
                uint2 p; p.x = packbf(R[r].x, R[r].y); p.y = packbf(R[r].z, R[r].w);
                *(uint2*)&sX[row*72 + k4] = p;
            }
            __syncthreads();
        }
    }
    __syncthreads();   // last MMA reads done before epilogue overwrites sX

    // Epilogue: scale + write K~/V^T/Q~; KsT/VsT alias sX (all reads done)
    __nv_bfloat16* KsT = sX;               // [2][32][72]  K~^T per chunk
    __nv_bfloat16* VsT = sX + 2*32*72;     // [2][32][72]  V^T per chunk
    #pragma unroll
    for (int mi = 0; mi < 2; mi++) {
        int rlo = wy*32 + mi*16 + g, rhi = rlo + 8;
        float lamL = Lam[rlo], lamH = Lam[rhi];
        float ksL = Lrs[rlo]/lamL, ksH = Lrs[rhi]/lamH;
        int chL = rlo >> 6, ulL = rlo & 63;
        int chH = rhi >> 6, ulH = rhi & 63;
        size_t tL = (size_t)(t0+rlo)*RR, tH = (size_t)(t0+rhi)*RR;
        #pragma unroll
        for (int ni = 0; ni < 6; ni++) {
            int c0 = wx*48 + ni*8 + 2*tig;
            float v0 = acc[mi][ni][0] + bcat[c0];
            float v1 = acc[mi][ni][1] + bcat[c0+1];
            float v2 = acc[mi][ni][2] + bcat[c0];
            float v3 = acc[mi][ni][3] + bcat[c0+1];
            if (c0 < 32) {
                v0 *= ksL; v1 *= ksL; v2 *= ksH; v3 *= ksH;
                *(uint32_t*)&g_Kb[tL + c0] = packbf(v0, v1);
                *(uint32_t*)&g_Kb[tH + c0] = packbf(v2, v3);
                KsT[(chL*32 + c0  )*72 + ulL] = __float2bfloat16(v0);
                KsT[(chL*32 + c0+1)*72 + ulL] = __float2bfloat16(v1);
                KsT[(chH*32 + c0  )*72 + ulH] = __float2bfloat16(v2);
                KsT[(chH*32 + c0+1)*72 + ulH] = __float2bfloat16(v3);
            } else if (c0 < 64) {
                int j0 = c0 - 32;
                __nv_bfloat16 b0 = __float2bfloat16(v0);
                __nv_bfloat16 b1 = __float2bfloat16(v1);
                __nv_bfloat16 b2 = __float2bfloat16(v2);
                __nv_bfloat16 b3 = __float2bfloat16(v3);
                VsT[(chL*32 + j0  )*72 + ulL] = b0;
                VsT[(chL*32 + j0+1)*72 + ulL] = b1;
                VsT[(chH*32 + j0  )*72 + ulH] = b2;
                VsT[(chH*32 + j0+1)*72 + ulH] = b3;
                size_t vbL = (size_t)(blockIdx.x*2 + chL)*2048;
                size_t vbH = (size_t)(blockIdx.x*2 + chH)*2048;
                g_VTb[vbL + (j0  )*64 + ulL] = b0;
                g_VTb[vbL + (j0+1)*64 + ulL] = b1;
                g_VTb[vbH + (j0  )*64 + ulH] = b2;
                g_VTb[vbH + (j0+1)*64 + ulH] = b3;
            } else {
                int r0 = c0 - 64;
                *(uint32_t*)&g_Qb[tL + r0] = packbf(v0*lamL, v1*lamL);
                *(uint32_t*)&g_Qb[tH + r0] = packbf(v2*lamH, v3*lamH);
            }
        }
    }
    __syncthreads();

    // B^T = (K~^T V)^T via MMA: per chunk 4 warps, warp tile m16 x n16, k=64
    {
        int ch = w >> 2, wl = w & 3;
        int wy2 = wl >> 1, wx2 = wl & 1;
        const __nv_bfloat16* Kt = KsT + ch*32*72;
        const __nv_bfloat16* Vt = VsT + ch*32*72;
        float accB[2][4];
        #pragma unroll
        for (int ni = 0; ni < 2; ni++)
            #pragma unroll
            for (int r = 0; r < 4; r++) accB[ni][r] = 0.f;
        #pragma unroll
        for (int ks = 0; ks < 4; ks++) {
            int kb = ks * 16;
            int rb = wy2 * 16;
            uint32_t a[4];
            a[0] = *(const uint32_t*)&Kt[(rb+g  )*72 + kb +     2*tig];
            a[1] = *(const uint32_t*)&Kt[(rb+8+g)*72 + kb +     2*tig];
            a[2] = *(const uint32_t*)&Kt[(rb+g  )*72 + kb + 8 + 2*tig];
            a[3] = *(const uint32_t*)&Kt[(rb+8+g)*72 + kb + 8 + 2*tig];
            #pragma unroll
            for (int ni = 0; ni < 2; ni++) {
                int nb = wx2*16 + ni*8;
                uint32_t b[2];
                b[0] = *(const uint32_t*)&Vt[(nb+g)*72 + kb +     2*tig];
                b[1] = *(const uint32_t*)&Vt[(nb+g)*72 + kb + 8 + 2*tig];
                mma16816(accB[ni], a, b);
            }
        }
        int cg = blockIdx.x*2 + ch;
        size_t base = (size_t)cg * 1024;
        #pragma unroll
        for (int ni = 0; ni < 2; ni++) {
            int i0 = wy2*16 + g, i1 = i0 + 8;
            int j0 = wx2*16 + ni*8 + 2*tig;
            g_BT[base + (j0  )*32 + i0] = accB[ni][0];
            g_BT[base + (j0+1)*32 + i0] = accB[ni][1];
            g_BT[base + (j0  )*32 + i1] = accB[ni][2];
            g_BT[base + (j0+1)*32 + i1] = accB[ni][3];
        }
        if (wl == 0 && lane == 0) g_gm[cg] = Lam[ch*64 + 63];
    }
}

// ---------------------------------------------------------------------------
// Scan phase A: per-segment local carry (zero init), depth 16.
// ---------------------------------------------------------------------------
__global__ __launch_bounds__(1024, 1) void k_scan_a()
{
    __shared__ float gs[SEG];
    const int b = blockIdx.x, e = threadIdx.x;
    if (e < SEG) gs[e] = g_gm[b*SEG + e];
    __syncthreads();
    const float* Bp = g_BT + (size_t)b*SEG*1024 + e;
    float bvv[SEG];
    #pragma unroll
    for (int c = 0; c < SEG; c++) bvv[c] = Bp[(size_t)c*1024];
    float s = 0.f;
    #pragma unroll
    for (int c = 0; c < SEG; c++) s = gs[c] * (s + bvv[c]);
    g_carry[(size_t)b*1024 + e] = s;
}

// ---------------------------------------------------------------------------
// Scan phase B (fused old scan2+scan3): block b folds carries 0..b-1 into
// incoming state p, then replays its segment emitting g_SpT.
// ---------------------------------------------------------------------------
__global__ __launch_bounds__(1024, 1) void k_scan_b()
{
    __shared__ float As[NSEG], gs[SEG];
    const int b = blockIdx.x, e = threadIdx.x;
    if (e < NSEG) {
        float p = 1.f;
        #pragma unroll
        for (int c = 0; c < SEG; c++) p *= g_gm[e*SEG + c];
        As[e] = p;
    } else if (e < NSEG + SEG) {
        gs[e - NSEG] = g_gm[b*SEG + (e - NSEG)];
    }
    // prefetch segment B values early (independent of carry fold)
    const float* Bp = g_BT + (size_t)b*SEG*1024 + e;
    float bvv[SEG];
    #pragma unroll
    for (int c = 0; c < SEG; c++) bvv[c] = Bp[(size_t)c*1024];
    __syncthreads();

    float p = 0.f;
    for (int bb = 0; bb < b; bb += 16) {
        float cv[16], av[16];
        #pragma unroll
        for (int j = 0; j < 16; j++) {
            bool ok = (bb + j < b);
            cv[j] = ok ? g_carry[(size_t)(bb+j)*1024 + e] : 0.f;
            av[j] = ok ? As[bb+j] : 1.f;
        }
        #pragma unroll
        for (int j = 0; j < 16; j++) p = fmaf(av[j], p, cv[j]);
    }

    float* Sp = g_SpT + (size_t)b*SEG*1024 + e;
    float s = p;
    #pragma unroll
    for (int c = 0; c < SEG; c++) {
        Sp[(size_t)c*1024] = s;
        s = gs[c] * (s + bvv[c]);
    }
}

// ---------------------------------------------------------------------------
// Kernel 3: 2 chunks/block, all-MMA, register-chained (one __syncthreads)
// ---------------------------------------------------------------------------
__global__ __launch_bounds__(256, 2) void k_out(
    const float* __restrict__ Wo, const float* __restrict__ bo,
    float* __restrict__ out)
{
    __shared__ __align__(16) __nv_bfloat16 sQ [2*64*40];
    __shared__ __align__(16) __nv_bfloat16 sK [2*64*40];
    __shared__ __align__(16) __nv_bfloat16 sVT[2*32*72];
    __shared__ __align__(16) __nv_bfloat16 sST[2*32*40];
    __shared__ __align__(16) __nv_bfloat16 sWo[56*40];
    __shared__ float sbo[56];

    const int tid = threadIdx.x;
    const int cg0 = blockIdx.x * 2;

    #pragma unroll
    for (int r = 0; r < 4; r++) {
        int slot = tid + 256*r;
        int ch = slot >> 9, s = slot & 511;
        int row = s >> 3, c4 = (s & 7) << 2;
        size_t gi = ((size_t)(cg0+ch)*64 + row)*RR + c4;
        *(uint2*)&sQ[(ch*64+row)*40 + c4] = *(const uint2*)&g_Qb[gi];
        *(uint2*)&sK[(ch*64+row)*40 + c4] = *(const uint2*)&g_Kb[gi];
    }
    #pragma unroll
    for (int r = 0; r < 4; r++) {
        int slot = tid + 256*r;
        int ch = slot >> 9, s = slot & 511;
        int row = s >> 4, c4 = (s & 15) << 2;
        *(uint2*)&sVT[(ch*32+row)*72 + c4] =
            *(const uint2*)&g_VTb[(size_t)(cg0+ch)*2048 + row*64 + c4];
    }
    #pragma unroll
    for (int r = 0; r < 2; r++) {
        int slot = tid + 256*r;
        int ch = slot >> 8, s = slot & 255;
        int row = s >> 3, c4 = (s & 7) << 2;
        float4 f = *(const float4*)&g_SpT[(size_t)(cg0+ch)*1024 + row*32 + c4];
        uint2 p; p.x = packbf(f.x, f.y); p.y = packbf(f.z, f.w);
        *(uint2*)&sST[(ch*32+row)*40 + c4] = p;
    }
    #pragma unroll
    for (int r = 0; r < 7; r++) {
        int idx = tid + 256*r;
        int m = idx >> 5, j = idx & 31;
        sWo[m*40 + j] = __float2bfloat16(m < MM ? Wo[m*RR + j] : 0.f);
    }
    if (tid < 56) sbo[tid] = (tid < MM) ? bo[tid] : 0.f;
    __syncthreads();

    const int lane = tid & 31, w = tid >> 5;
    const int g = lane >> 2, tig = lane & 3;
    const int ch = w >> 2, wr = w & 3;
    const __nv_bfloat16* Q  = sQ  + ch*64*40;
    const __nv_bfloat16* K  = sK  + ch*64*40;
    const __nv_bfloat16* VT = sVT + ch*32*72;
    const __nv_bfloat16* ST = sST + ch*32*40;
    const int rb = wr * 16;

    uint32_t aq[2][4];
    float accA[8][4];
    #pragma unroll
    for (int ni = 0; ni < 8; ni++)
        #pragma unroll
        for (int r = 0; r < 4; r++) accA[ni][r] = 0.f;
    #pragma unroll
    for (int ks = 0; ks < 2; ks++) {
        int kb = ks * 16;
        aq[ks][0] = *(const uint32_t*)&Q[(rb+g  )*40 + kb +     2*tig];
        aq[ks][1] = *(const uint32_t*)&Q[(rb+8+g)*40 + kb +     2*tig];
        aq[ks][2] = *(const uint32_t*)&Q[(rb+g  )*40 + kb + 8 + 2*tig];
        aq[ks][3] = *(const uint32_t*)&Q[(rb+8+g)*40 + kb + 8 + 2*tig];
        #pragma unroll
        for (int ni = 0; ni < 8; ni++) {
            uint32_t b[2];
            b[0] = *(const uint32_t*)&K[(ni*8+g)*40 + kb +     2*tig];
            b[1] = *(const uint32_t*)&K[(ni*8+g)*40 + kb + 8 + 2*tig];
            mma16816(accA[ni], aq[ks], b);
        }
    }
    uint32_t aA[4][4];
    {
        int ulo = rb + g, uhi = rb + g + 8;
        #pragma unroll
        for (int ni = 0; ni < 8; ni++) {
            int s0 = ni*8 + 2*tig, s1 = s0 + 1;
            float m0 = (s0 <= ulo) ? accA[ni][0] : 0.f;
            float m1 = (s1 <= ulo) ? accA[ni][1] : 0.f;
            float m2 = (s0 <= uhi) ? accA[ni][2] : 0.f;
            float m3 = (s1 <= uhi) ? accA[ni][3] : 0.f;
            int ks2 = ni >> 1;
            if ((ni & 1) == 0) { aA[ks2][0] = packbf(m0, m1); aA[ks2][1] = packbf(m2, m3); }
            else               { aA[ks2][2] = packbf(m0, m1); aA[ks2][3] = packbf(m2, m3); }
        }
    }
    float accO[4][4];
    #pragma unroll
    for (int ni = 0; ni < 4; ni++)
        #pragma unroll
        for (int r = 0; r < 4; r++) accO[ni][r] = 0.f;
    #pragma unroll
    for (int ks = 0; ks < 2; ks++) {
        int kb = ks * 16;
        #pragma unroll
        for (int ni = 0; ni < 4; ni++) {
            uint32_t b[2];
            b[0] = *(const uint32_t*)&ST[(ni*8+g)*40 + kb +     2*tig];
            b[1] = *(const uint32_t*)&ST[(ni*8+g)*40 + kb + 8 + 2*tig];
            mma16816(accO[ni], aq[ks], b);
        }
    }
    #pragma unroll
    for (int ks = 0; ks < 4; ks++) {
        int kb = ks * 16;
        #pragma unroll
        for (int ni = 0; ni < 4; ni++) {
            uint32_t b[2];
            b[0] = *(const uint32_t*)&VT[(ni*8+g)*72 + kb +     2*tig];
            b[1] = *(const uint32_t*)&VT[(ni*8+g)*72 + kb + 8 + 2*tig];
            mma16816(accO[ni], aA[ks], b);
        }
    }
    uint32_t aO[2][4];
    #pragma unroll
    for (int ks2 = 0; ks2 < 2; ks2++) {
        aO[ks2][0] = packbf(accO[2*ks2  ][0], accO[2*ks2  ][1]);
        aO[ks2][1] = packbf(accO[2*ks2  ][2], accO[2*ks2  ][3]);
        aO[ks2][2] = packbf(accO[2*ks2+1][0], accO[2*ks2+1][1]);
        aO[ks2][3] = packbf(accO[2*ks2+1][2], accO[2*ks2+1][3]);
    }
    float accH[7][4];
    #pragma unroll
    for (int ni = 0; ni < 7; ni++)
        #pragma unroll
        for (int r = 0; r < 4; r++) accH[ni][r] = 0.f;
    #pragma unroll
    for (int ks = 0; ks < 2; ks++) {
        int kb = ks * 16;
        #pragma unroll
        for (int ni = 0; ni < 7; ni++) {
            uint32_t b[2];
            b[0] = *(const uint32_t*)&sWo[(ni*8+g)*40 + kb +     2*tig];
            b[1] = *(const uint32_t*)&sWo[(ni*8+g)*40 + kb + 8 + 2*tig];
            mma16816(accH[ni], aO[ks], b);
        }
    }
    {
        size_t t0c = (size_t)(cg0 + ch) * 64;
        size_t rl = (t0c + rb + g) * MM;
        size_t rh = (t0c + rb + g + 8) * MM;
        #pragma unroll
        for (int ni = 0; ni < 7; ni++) {
            int m0 = ni*8 + 2*tig, m1 = m0 + 1;
            if (m0 < MM) {
                out[rl + m0] = 1.f + tanh_fast(accH[ni][0] + sbo[m0]);
                out[rh + m0] = 1.f + tanh_fast(accH[ni][2] + sbo[m0]);
            }
            if (m1 < MM) {
                out[rl + m1] = 1.f + tanh_fast(accH[ni][1] + sbo[m1]);
                out[rh + m1] = 1.f + tanh_fast(accH[ni][3] + sbo[m1]);
            }
        }
    }
}

// ---------------------------------------------------------------------------
extern "C" void kernel_launch(void* const* d_in, const int* in_sizes, int n_in,
                              void* d_out, int out_size)
{
    const float* X  = (const float*)d_in[0];
    const float* lr = (const float*)d_in[1];
    const float* dc = (const float*)d_in[2];
    const float* Wk = (const float*)d_in[3];
    const float* bk = (const float*)d_in[4];
    const float* Wv = (const float*)d_in[5];
    const float* bv = (const float*)d_in[6];
    const float* Wq = (const float*)d_in[7];
    const float* bq = (const float*)d_in[8];
    const float* Wo = (const float*)d_in[9];
    const float* bo = (const float*)d_in[10];
    float* out = (float*)d_out;

    const int smem1 = (96*264 + 128*72) * 2;   // 69120 B
    cudaFuncSetAttribute(k_proj, cudaFuncAttributeMaxDynamicSharedMemorySize, smem1);

    k_proj<<<NCK/2, 256, smem1>>>(X, lr, dc, Wk, bk, Wv, bv, Wq, bq);
    k_scan_a<<<NSEG, 1024>>>();
    k_scan_b<<<NSEG, 1024>>>();
    k_out<<<NCK/2, 256>>>(Wo, bo, out);
    (void)in_sizes; (void)n_in; (void)out_size;
}

// round 7
// speedup vs baseline: 9.3759x; 1.0377x over previous
#include <cuda_runtime.h>
#include <cuda_bf16.h>
#include <math.h>
#include <stdint.h>

#define TT 65536
#define DD 256
#define RR 32
#define MM 52
#define CC 64
#define NCK 1024
#define SEG 16
#define NSEG (NCK/SEG)   // 64

// Scratch (device globals; no allocation allowed)
__device__ __align__(16) __nv_bfloat16 g_Qb [TT*RR];   // Lambda_u * q_u   [t][r]
__device__ __align__(16) __nv_bfloat16 g_Kb [TT*RR];   // (l/Lambda)*k     [t][r]
__device__ __align__(16) __nv_bfloat16 g_VTb[TT*RR];   // per-chunk V^T    [chunk][j=32][u=64]
__device__ __align__(16) float g_BT [NCK*RR*RR];       // per-chunk (K~^T V)^T  [chunk][j][i]
__device__ float g_gm[NCK];                            // per-chunk Lambda_C
__device__ __align__(16) float g_carry[NSEG*1024];     // segment-local carries

__device__ __forceinline__ uint32_t packbf(float a, float b) {
    __nv_bfloat162 h = __floats2bfloat162_rn(a, b);
    return *reinterpret_cast<uint32_t*>(&h);
}
__device__ __forceinline__ float tanh_fast(float x) {
    float y; asm("tanh.approx.f32 %0, %1;" : "=f"(y) : "f"(x)); return y;
}
__device__ __forceinline__ void mma16816(float* c, const uint32_t* a, const uint32_t* b) {
    asm volatile("mma.sync.aligned.m16n8k16.row.col.f32.bf16.bf16.f32 "
        "{%0,%1,%2,%3}, {%4,%5,%6,%7}, {%8,%9}, {%0,%1,%2,%3};"
        : "+f"(c[0]), "+f"(c[1]), "+f"(c[2]), "+f"(c[3])
        : "r"(a[0]), "r"(a[1]), "r"(a[2]), "r"(a[3]), "r"(b[0]), "r"(b[1]));
}

// ---------------------------------------------------------------------------
// Kernel 1: 2 chunks (128 rows) per block. bf16 MMA projections + B + gamma.
// W preloaded once (96x256 bf16); X software-pipelined via register prefetch.
// ---------------------------------------------------------------------------
__global__ __launch_bounds__(256, 2) void k_proj(
    const float* __restrict__ X,  const float* __restrict__ lr,
    const float* __restrict__ dec,
    const float* __restrict__ Wk, const float* __restrict__ bk,
    const float* __restrict__ Wv, const float* __restrict__ bv,
    const float* __restrict__ Wq, const float* __restrict__ bq)
{
    extern __shared__ __align__(16) __nv_bfloat16 dsm[];
    __nv_bfloat16* sW = dsm;                 // 96 x 264  (full K=256 + pad 8)
    __nv_bfloat16* sX = dsm + 96*264;        // 128 x 72  (one 64-col k-slab)
    __shared__ float Lam[128], Lrs[128], Dcs[128], bcat[96];

    const int tid  = threadIdx.x;
    const int lane = tid & 31, w = tid >> 5;
    const int g = lane >> 2, tig = lane & 3;
    const int t0 = blockIdx.x * 128;

    if (tid < 96)
        bcat[tid] = (tid < 32) ? bk[tid] : (tid < 64 ? bv[tid-32] : bq[tid-64]);
    if (tid < 128) Lrs[tid] = lr[t0 + tid];
    else           Dcs[tid-128] = dec[t0 + tid - 128];

    // Prefetch X slab 0 into registers (8 float4 per thread)
    float4 R[8];
    #pragma unroll
    for (int r = 0; r < 8; r++) {
        int slot = tid + 256*r;
        int row = slot >> 4, k4 = (slot & 15) << 2;
        R[r] = *(const float4*)&X[(size_t)(t0+row)*DD + k4];
    }

    // Preload full W (96x256 f32 -> bf16), 24 float4 per thread
    #pragma unroll
    for (int r = 0; r < 24; r++) {
        int slot = tid + 256*r;                  // 6144 slots
        int row = slot >> 6, k4 = (slot & 63) << 2;
        const float* Wsrc = (row < 32) ? Wk : (row < 64 ? Wv : Wq);
        float4 w4 = *(const float4*)&Wsrc[(row & 31)*DD + k4];
        uint2 p; p.x = packbf(w4.x, w4.y); p.y = packbf(w4.z, w4.w);
        *(uint2*)&sW[row*264 + k4] = p;
    }

    __syncthreads();           // Dcs visible
    if (tid < 2) {
        float p = 1.f;
        #pragma unroll
        for (int u = 0; u < 64; u++) { p *= (1.f - Dcs[64*tid + u]); Lam[64*tid + u] = p; }
    }

    // Store X slab 0
    #pragma unroll
    for (int r = 0; r < 8; r++) {
        int slot = tid + 256*r;
        int row = slot >> 4, k4 = (slot & 15) << 2;
        uint2 p; p.x = packbf(R[r].x, R[r].y); p.y = packbf(R[r].z, R[r].w);
        *(uint2*)&sX[row*72 + k4] = p;
    }
    __syncthreads();           // X slab 0 + W + Lam all visible

    const int wy = w >> 1, wx = w & 1;   // warp tile: 32 rows x 48 cols
    float acc[2][6][4];
    #pragma unroll
    for (int mi = 0; mi < 2; mi++)
        #pragma unroll
        for (int ni = 0; ni < 6; ni++)
            #pragma unroll
            for (int r = 0; r < 4; r++) acc[mi][ni][r] = 0.f;

    #pragma unroll
    for (int it = 0; it < 4; it++) {
        // Prefetch next X slab (LDG in flight during MMA section)
        if (it < 3) {
            int kk0n = (it+1) * 64;
            #pragma unroll
            for (int r = 0; r < 8; r++) {
                int slot = tid + 256*r;
                int row = slot >> 4, k4 = (slot & 15) << 2;
                R[r] = *(const float4*)&X[(size_t)(t0+row)*DD + kk0n + k4];
            }
        }
        // MMA over current slab
        #pragma unroll
        for (int ks = 0; ks < 4; ks++) {
            int kbX = ks * 16;
            int kbW = it * 64 + ks * 16;
            uint32_t a[2][4];
            #pragma unroll
            for (int mi = 0; mi < 2; mi++) {
                int rb = wy*32 + mi*16;
                a[mi][0] = *(const uint32_t*)&sX[(rb+g  )*72 + kbX +     2*tig];
                a[mi][1] = *(const uint32_t*)&sX[(rb+8+g)*72 + kbX +     2*tig];
                a[mi][2] = *(const uint32_t*)&sX[(rb+g  )*72 + kbX + 8 + 2*tig];
                a[mi][3] = *(const uint32_t*)&sX[(rb+8+g)*72 + kbX + 8 + 2*tig];
            }
            #pragma unroll
            for (int ni = 0; ni < 6; ni++) {
                int nb = wx*48 + ni*8;
                uint32_t b[2];
                b[0] = *(const uint32_t*)&sW[(nb+g)*264 + kbW +     2*tig];
                b[1] = *(const uint32_t*)&sW[(nb+g)*264 + kbW + 8 + 2*tig];
                mma16816(acc[0][ni], a[0], b);
                mma16816(acc[1][ni], a[1], b);
            }
        }
        if (it < 3) {
            __syncthreads();   // all warps done reading sX
            #pragma unroll
            for (int r = 0; r < 8; r++) {
                int slot = tid + 256*r;
                int row = slot >> 4, k4 = (slot & 15) << 2;
                uint2 p; p.x = packbf(R[r].x, R[r].y); p.y = packbf(R[r].z, R[r].w);
                *(uint2*)&sX[row*72 + k4] = p;
            }
            __syncthreads();
        }
    }
    __syncthreads();   // last MMA reads done before epilogue overwrites sX

    // Epilogue: scale + write K~/V^T/Q~; KsT/VsT alias sX (all reads done)
    __nv_bfloat16* KsT = sX;               // [2][32][72]  K~^T per chunk
    __nv_bfloat16* VsT = sX + 2*32*72;     // [2][32][72]  V^T per chunk
    #pragma unroll
    for (int mi = 0; mi < 2; mi++) {
        int rlo = wy*32 + mi*16 + g, rhi = rlo + 8;
        float lamL = Lam[rlo], lamH = Lam[rhi];
        float ksL = Lrs[rlo]/lamL, ksH = Lrs[rhi]/lamH;
        int chL = rlo >> 6, ulL = rlo & 63;
        int chH = rhi >> 6, ulH = rhi & 63;
        size_t tL = (size_t)(t0+rlo)*RR, tH = (size_t)(t0+rhi)*RR;
        #pragma unroll
        for (int ni = 0; ni < 6; ni++) {
            int c0 = wx*48 + ni*8 + 2*tig;
            float v0 = acc[mi][ni][0] + bcat[c0];
            float v1 = acc[mi][ni][1] + bcat[c0+1];
            float v2 = acc[mi][ni][2] + bcat[c0];
            float v3 = acc[mi][ni][3] + bcat[c0+1];
            if (c0 < 32) {
                v0 *= ksL; v1 *= ksL; v2 *= ksH; v3 *= ksH;
                *(uint32_t*)&g_Kb[tL + c0] = packbf(v0, v1);
                *(uint32_t*)&g_Kb[tH + c0] = packbf(v2, v3);
                KsT[(chL*32 + c0  )*72 + ulL] = __float2bfloat16(v0);
                KsT[(chL*32 + c0+1)*72 + ulL] = __float2bfloat16(v1);
                KsT[(chH*32 + c0  )*72 + ulH] = __float2bfloat16(v2);
                KsT[(chH*32 + c0+1)*72 + ulH] = __float2bfloat16(v3);
            } else if (c0 < 64) {
                int j0 = c0 - 32;
                __nv_bfloat16 b0 = __float2bfloat16(v0);
                __nv_bfloat16 b1 = __float2bfloat16(v1);
                __nv_bfloat16 b2 = __float2bfloat16(v2);
                __nv_bfloat16 b3 = __float2bfloat16(v3);
                VsT[(chL*32 + j0  )*72 + ulL] = b0;
                VsT[(chL*32 + j0+1)*72 + ulL] = b1;
                VsT[(chH*32 + j0  )*72 + ulH] = b2;
                VsT[(chH*32 + j0+1)*72 + ulH] = b3;
                size_t vbL = (size_t)(blockIdx.x*2 + chL)*2048;
                size_t vbH = (size_t)(blockIdx.x*2 + chH)*2048;
                g_VTb[vbL + (j0  )*64 + ulL] = b0;
                g_VTb[vbL + (j0+1)*64 + ulL] = b1;
                g_VTb[vbH + (j0  )*64 + ulH] = b2;
                g_VTb[vbH + (j0+1)*64 + ulH] = b3;
            } else {
                int r0 = c0 - 64;
                *(uint32_t*)&g_Qb[tL + r0] = packbf(v0*lamL, v1*lamL);
                *(uint32_t*)&g_Qb[tH + r0] = packbf(v2*lamH, v3*lamH);
            }
        }
    }
    __syncthreads();

    // B^T = (K~^T V)^T via MMA: per chunk 4 warps, warp tile m16 x n16, k=64
    {
        int ch = w >> 2, wl = w & 3;
        int wy2 = wl >> 1, wx2 = wl & 1;
        const __nv_bfloat16* Kt = KsT + ch*32*72;
        const __nv_bfloat16* Vt = VsT + ch*32*72;
        float accB[2][4];
        #pragma unroll
        for (int ni = 0; ni < 2; ni++)
            #pragma unroll
            for (int r = 0; r < 4; r++) accB[ni][r] = 0.f;
        #pragma unroll
        for (int ks = 0; ks < 4; ks++) {
            int kb = ks * 16;
            int rb = wy2 * 16;
            uint32_t a[4];
            a[0] = *(const uint32_t*)&Kt[(rb+g  )*72 + kb +     2*tig];
            a[1] = *(const uint32_t*)&Kt[(rb+8+g)*72 + kb +     2*tig];
            a[2] = *(const uint32_t*)&Kt[(rb+g  )*72 + kb + 8 + 2*tig];
            a[3] = *(const uint32_t*)&Kt[(rb+8+g)*72 + kb + 8 + 2*tig];
            #pragma unroll
            for (int ni = 0; ni < 2; ni++) {
                int nb = wx2*16 + ni*8;
                uint32_t b[2];
                b[0] = *(const uint32_t*)&Vt[(nb+g)*72 + kb +     2*tig];
                b[1] = *(const uint32_t*)&Vt[(nb+g)*72 + kb + 8 + 2*tig];
                mma16816(accB[ni], a, b);
            }
        }
        int cg = blockIdx.x*2 + ch;
        size_t base = (size_t)cg * 1024;
        #pragma unroll
        for (int ni = 0; ni < 2; ni++) {
            int i0 = wy2*16 + g, i1 = i0 + 8;
            int j0 = wx2*16 + ni*8 + 2*tig;
            g_BT[base + (j0  )*32 + i0] = accB[ni][0];
            g_BT[base + (j0+1)*32 + i0] = accB[ni][1];
            g_BT[base + (j0  )*32 + i1] = accB[ni][2];
            g_BT[base + (j0+1)*32 + i1] = accB[ni][3];
        }
        if (wl == 0 && lane == 0) g_gm[cg] = Lam[ch*64 + 63];
    }
}

// ---------------------------------------------------------------------------
// Scan phase A: per-segment local carry (zero init), depth 16.
// ---------------------------------------------------------------------------
__global__ __launch_bounds__(1024, 1) void k_scan_a()
{
    __shared__ float gs[SEG];
    const int b = blockIdx.x, e = threadIdx.x;
    if (e < SEG) gs[e] = g_gm[b*SEG + e];
    __syncthreads();
    const float* Bp = g_BT + (size_t)b*SEG*1024 + e;
    float bvv[SEG];
    #pragma unroll
    for (int c = 0; c < SEG; c++) bvv[c] = Bp[(size_t)c*1024];
    float s = 0.f;
    #pragma unroll
    for (int c = 0; c < SEG; c++) s = gs[c] * (s + bvv[c]);
    g_carry[(size_t)b*1024 + e] = s;
}

// ---------------------------------------------------------------------------
// Kernel 3 (fused with scan phase B): 4 chunks/block, grid 256 = single wave.
// Block folds segment carries + replays local B steps to build its 4 incoming
// states, then per-chunk all-MMA chain A -> O -> head -> 1+tanh.
// ---------------------------------------------------------------------------
__global__ __launch_bounds__(256, 3) void k_out(
    const float* __restrict__ Wo, const float* __restrict__ bo,
    float* __restrict__ out)
{
    extern __shared__ __align__(16) __nv_bfloat16 osm[];
    __nv_bfloat16* sQ  = osm;                 // 4*64*40 = 10240
    __nv_bfloat16* sK  = sQ  + 10240;         // 10240
    __nv_bfloat16* sVT = sK  + 10240;         // 4*32*72 = 9216
    __nv_bfloat16* sST = sVT + 9216;          // 4*32*40 = 5120
    __nv_bfloat16* sWo = sST + 5120;          // 56*40   = 2240
    __shared__ float sbo[56];
    __shared__ float sAs[NSEG];
    __shared__ float gsc[SEG];

    const int tid   = threadIdx.x;
    const int cg0   = blockIdx.x * 4;         // first chunk of this block
    const int b_seg = blockIdx.x >> 2;        // segment index
    const int p0    = (blockIdx.x & 3) * 4;   // seg-local offset of cg0

    // Small smem: segment products, own-segment gammas, bias
    if (tid < NSEG) {
        float pp = 1.f;
        #pragma unroll
        for (int c = 0; c < SEG; c++) pp *= g_gm[tid*SEG + c];
        sAs[tid] = pp;
    } else if (tid < NSEG + SEG) {
        gsc[tid - NSEG] = g_gm[b_seg*SEG + (tid - NSEG)];
    } else if (tid < NSEG + SEG + 56) {
        int m = tid - NSEG - SEG;
        sbo[m] = (m < MM) ? bo[m] : 0.f;
    }

    // Stage Q, K (bf16, 4 chunks x 64 rows x 32)
    #pragma unroll
    for (int r = 0; r < 8; r++) {
        int slot = tid + 256*r;                 // 2048 slots
        int ch = slot >> 9, s = slot & 511;
        int row = s >> 3, c4 = (s & 7) << 2;
        size_t gi = ((size_t)(cg0+ch)*64 + row)*RR + c4;
        *(uint2*)&sQ[(ch*64+row)*40 + c4] = *(const uint2*)&g_Qb[gi];
        *(uint2*)&sK[(ch*64+row)*40 + c4] = *(const uint2*)&g_Kb[gi];
    }
    // Stage V^T (4 chunks x 32 x 64)
    #pragma unroll
    for (int r = 0; r < 8; r++) {
        int slot = tid + 256*r;                 // 2048 slots
        int ch = slot >> 9, s = slot & 511;
        int row = s >> 4, c4 = (s & 15) << 2;
        *(uint2*)&sVT[(ch*32+row)*72 + c4] =
            *(const uint2*)&g_VTb[(size_t)(cg0+ch)*2048 + row*64 + c4];
    }
    // Stage Wo (fp32 -> bf16, zero-padded to 56 rows)
    #pragma unroll
    for (int r = 0; r < 7; r++) {
        int idx = tid + 256*r;                  // 1792 = 56*32
        int m = idx >> 5, jj = idx & 31;
        sWo[m*40 + jj] = __float2bfloat16(m < MM ? Wo[m*RR + jj] : 0.f);
    }
    __syncthreads();

    // ---- Fold carries of preceding segments (batch-8 pipelined, float4/thread)
    float pf[4] = {0.f, 0.f, 0.f, 0.f};
    for (int bb = 0; bb < b_seg; bb += 8) {
        float4 cv[8]; float av[8];
        #pragma unroll
        for (int jq = 0; jq < 8; jq++) {
            bool ok = (bb + jq) < b_seg;
            cv[jq] = ok ? *(const float4*)&g_carry[(size_t)(bb+jq)*1024 + tid*4]
                        : make_float4(0.f, 0.f, 0.f, 0.f);
            av[jq] = ok ? sAs[bb+jq] : 1.f;
        }
        #pragma unroll
        for (int jq = 0; jq < 8; jq++) {
            pf[0] = fmaf(av[jq], pf[0], cv[jq].x);
            pf[1] = fmaf(av[jq], pf[1], cv[jq].y);
            pf[2] = fmaf(av[jq], pf[2], cv[jq].z);
            pf[3] = fmaf(av[jq], pf[3], cv[jq].w);
        }
    }
    // ---- Replay seg-local chunks 0..p0-1 (batch-4)
    for (int cc = 0; cc < p0; cc += 4) {
        float4 bv[4];
        #pragma unroll
        for (int jq = 0; jq < 4; jq++)
            bv[jq] = *(const float4*)&g_BT[(size_t)(b_seg*SEG + cc + jq)*1024 + tid*4];
        #pragma unroll
        for (int jq = 0; jq < 4; jq++) {
            float gv = gsc[cc + jq];
            pf[0] = gv*(pf[0] + bv[jq].x);
            pf[1] = gv*(pf[1] + bv[jq].y);
            pf[2] = gv*(pf[2] + bv[jq].z);
            pf[3] = gv*(pf[3] + bv[jq].w);
        }
    }
    // ---- Emit 4 incoming states into sST (bf16), stepping through own chunks
    {
        const int jrow = tid >> 3, i0 = (tid & 7) << 2;
        float4 b3[3];
        #pragma unroll
        for (int q = 0; q < 3; q++)
            b3[q] = *(const float4*)&g_BT[(size_t)(cg0 + q)*1024 + tid*4];
        __nv_bfloat16* d0 = &sST[(0*32 + jrow)*40 + i0];
        *(uint32_t*)&d0[0] = packbf(pf[0], pf[1]);
        *(uint32_t*)&d0[2] = packbf(pf[2], pf[3]);
        #pragma unroll
        for (int q = 0; q < 3; q++) {
            float gv = gsc[p0 + q];
            pf[0] = gv*(pf[0] + b3[q].x);
            pf[1] = gv*(pf[1] + b3[q].y);
            pf[2] = gv*(pf[2] + b3[q].z);
            pf[3] = gv*(pf[3] + b3[q].w);
            __nv_bfloat16* d = &sST[((q+1)*32 + jrow)*40 + i0];
            *(uint32_t*)&d[0] = packbf(pf[0], pf[1]);
            *(uint32_t*)&d[2] = packbf(pf[2], pf[3]);
        }
    }
    __syncthreads();

    // ---- MMA phase: 8 warps, each does 2 chunks sequentially (16 rows each)
    const int lane = tid & 31, w = tid >> 5;
    const int g = lane >> 2, tig = lane & 3;
    const int rb = (w & 3) * 16;

    for (int ch2 = 0; ch2 < 2; ch2++) {
        const int ci = (w >> 2)*2 + ch2;
        const __nv_bfloat16* Q  = sQ  + ci*2560;
        const __nv_bfloat16* K  = sK  + ci*2560;
        const __nv_bfloat16* VT = sVT + ci*2304;
        const __nv_bfloat16* ST = sST + ci*1280;

        uint32_t aq[2][4];
        float accA[8][4];
        #pragma unroll
        for (int ni = 0; ni < 8; ni++)
            #pragma unroll
            for (int r = 0; r < 4; r++) accA[ni][r] = 0.f;
        #pragma unroll
        for (int ks = 0; ks < 2; ks++) {
            int kb = ks * 16;
            aq[ks][0] = *(const uint32_t*)&Q[(rb+g  )*40 + kb +     2*tig];
            aq[ks][1] = *(const uint32_t*)&Q[(rb+8+g)*40 + kb +     2*tig];
            aq[ks][2] = *(const uint32_t*)&Q[(rb+g  )*40 + kb + 8 + 2*tig];
            aq[ks][3] = *(const uint32_t*)&Q[(rb+8+g)*40 + kb + 8 + 2*tig];
            #pragma unroll
            for (int ni = 0; ni < 8; ni++) {
                uint32_t b[2];
                b[0] = *(const uint32_t*)&K[(ni*8+g)*40 + kb +     2*tig];
                b[1] = *(const uint32_t*)&K[(ni*8+g)*40 + kb + 8 + 2*tig];
                mma16816(accA[ni], aq[ks], b);
            }
        }
        uint32_t aA[4][4];
        {
            int ulo = rb + g, uhi = rb + g + 8;
            #pragma unroll
            for (int ni = 0; ni < 8; ni++) {
                int s0 = ni*8 + 2*tig, s1 = s0 + 1;
                float m0 = (s0 <= ulo) ? accA[ni][0] : 0.f;
                float m1 = (s1 <= ulo) ? accA[ni][1] : 0.f;
                float m2 = (s0 <= uhi) ? accA[ni][2] : 0.f;
                float m3 = (s1 <= uhi) ? accA[ni][3] : 0.f;
                int ks2 = ni >> 1;
                if ((ni & 1) == 0) { aA[ks2][0] = packbf(m0, m1); aA[ks2][1] = packbf(m2, m3); }
                else               { aA[ks2][2] = packbf(m0, m1); aA[ks2][3] = packbf(m2, m3); }
            }
        }
        float accO[4][4];
        #pragma unroll
        for (int ni = 0; ni < 4; ni++)
            #pragma unroll
            for (int r = 0; r < 4; r++) accO[ni][r] = 0.f;
        #pragma unroll
        for (int ks = 0; ks < 2; ks++) {
            int kb = ks * 16;
            #pragma unroll
            for (int ni = 0; ni < 4; ni++) {
                uint32_t b[2];
                b[0] = *(const uint32_t*)&ST[(ni*8+g)*40 + kb +     2*tig];
                b[1] = *(const uint32_t*)&ST[(ni*8+g)*40 + kb + 8 + 2*tig];
                mma16816(accO[ni], aq[ks], b);
            }
        }
        #pragma unroll
        for (int ks = 0; ks < 4; ks++) {
            int kb = ks * 16;
            #pragma unroll
            for (int ni = 0; ni < 4; ni++) {
                uint32_t b[2];
                b[0] = *(const uint32_t*)&VT[(ni*8+g)*72 + kb +     2*tig];
                b[1] = *(const uint32_t*)&VT[(ni*8+g)*72 + kb + 8 + 2*tig];
                mma16816(accO[ni], aA[ks], b);
            }
        }
        uint32_t aO[2][4];
        #pragma unroll
        for (int ks2 = 0; ks2 < 2; ks2++) {
            aO[ks2][0] = packbf(accO[2*ks2  ][0], accO[2*ks2  ][1]);
            aO[ks2][1] = packbf(accO[2*ks2  ][2], accO[2*ks2  ][3]);
            aO[ks2][2] = packbf(accO[2*ks2+1][0], accO[2*ks2+1][1]);
            aO[ks2][3] = packbf(accO[2*ks2+1][2], accO[2*ks2+1][3]);
        }
        float accH[7][4];
        #pragma unroll
        for (int ni = 0; ni < 7; ni++)
            #pragma unroll
            for (int r = 0; r < 4; r++) accH[ni][r] = 0.f;
        #pragma unroll
        for (int ks = 0; ks < 2; ks++) {
            int kb = ks * 16;
            #pragma unroll
            for (int ni = 0; ni < 7; ni++) {
                uint32_t b[2];
                b[0] = *(const uint32_t*)&sWo[(ni*8+g)*40 + kb +     2*tig];
                b[1] = *(const uint32_t*)&sWo[(ni*8+g)*40 + kb + 8 + 2*tig];
                mma16816(accH[ni], aO[ks], b);
            }
        }
        {
            size_t t0c = (size_t)(cg0 + ci) * 64;
            size_t rl = (t0c + rb + g) * MM;
            size_t rh = (t0c + rb + g + 8) * MM;
            #pragma unroll
            for (int ni = 0; ni < 7; ni++) {
                int m0 = ni*8 + 2*tig, m1 = m0 + 1;
                if (m0 < MM) {
                    out[rl + m0] = 1.f + tanh_fast(accH[ni][0] + sbo[m0]);
                    out[rh + m0] = 1.f + tanh_fast(accH[ni][2] + sbo[m0]);
                }
                if (m1 < MM) {
                    out[rl + m1] = 1.f + tanh_fast(accH[ni][1] + sbo[m1]);
                    out[rh + m1] = 1.f + tanh_fast(accH[ni][3] + sbo[m1]);
                }
            }
        }
    }
}

// ---------------------------------------------------------------------------
extern "C" void kernel_launch(void* const* d_in, const int* in_sizes, int n_in,
                              void* d_out, int out_size)
{
    const float* X  = (const float*)d_in[0];
    const float* lr = (const float*)d_in[1];
    const float* dc = (const float*)d_in[2];
    const float* Wk = (const float*)d_in[3];
    const float* bk = (const float*)d_in[4];
    const float* Wv = (const float*)d_in[5];
    const float* bv = (const float*)d_in[6];
    const float* Wq = (const float*)d_in[7];
    const float* bq = (const float*)d_in[8];
    const float* Wo = (const float*)d_in[9];
    const float* bo = (const float*)d_in[10];
    float* out = (float*)d_out;

    const int smem1 = (96*264 + 128*72) * 2;                      // 69120 B
    const int smem3 = (10240 + 10240 + 9216 + 5120 + 2240) * 2;   // 74112 B
    cudaFuncSetAttribute(k_proj, cudaFuncAttributeMaxDynamicSharedMemorySize, smem1);
    cudaFuncSetAttribute(k_out,  cudaFuncAttributeMaxDynamicSharedMemorySize, smem3);

    k_proj<<<NCK/2, 256, smem1>>>(X, lr, dc, Wk, bk, Wv, bv, Wq, bq);
    k_scan_a<<<NSEG, 1024>>>();
    k_out<<<NCK/4, 256, smem3>>>(Wo, bo, out);
    (void)in_sizes; (void)n_in; (void)out_size;
}